// round 4
// baseline (speedup 1.0000x reference)
#include <cuda_runtime.h>
#include <math.h>

// Problem constants
#define BATCH 4
#define SEQ   2048
#define DMODEL 512
#define NHEAD 8
#define HDIM  64
#define DFF   2048
#define MROWS (BATCH * SEQ)   // 8192

// ---------------- scratch (static device arrays; no allocation allowed) ----
__device__ float g_q[BATCH * NHEAD * SEQ * HDIM];   // [BH, T, 64]
__device__ float g_k[BATCH * NHEAD * SEQ * HDIM];
__device__ float g_v[BATCH * NHEAD * SEQ * HDIM];
__device__ float g_ctx[MROWS * DMODEL];             // [B,T,D]
__device__ float g_tmp[MROWS * DMODEL];             // pre-LN buffer (reused)
__device__ float g_x1[MROWS * DMODEL];              // post-LN1 (FFN input + residual2)
__device__ float g_h[MROWS * DFF];                  // FFN hidden

// ---------------- generic tiled fp32 GEMM: C = A (MxK) * B^T (B is NxK) ----
// BM=BN=128, BK=16, 256 threads, 8x8 per thread (interleaved mapping).
// EPI 0: heads scatter + bias -> out[((b*8+h)*T + t)*64 + dh]
// EPI 1: bias + residual      -> out[m*N+n] = v + bias[n] + res[m*N+n]
// EPI 2: bias + exact GELU    -> out[m*N+n] = gelu(v + bias[n])
template <int EPI>
__global__ __launch_bounds__(256)
void gemm_kernel(const float* __restrict__ A, const float* __restrict__ B,
                 const float* __restrict__ bias, const float* __restrict__ res,
                 float* __restrict__ out, int M, int N, int K) {
    __shared__ float sA[128 * 17];
    __shared__ float sB[128 * 17];

    const int tid = threadIdx.x;
    const int tx = tid & 15;          // 0..15
    const int ty = tid >> 4;          // 0..15
    const int bm = blockIdx.y * 128;
    const int bn = blockIdx.x * 128;

    float acc[8][8];
#pragma unroll
    for (int i = 0; i < 8; ++i)
#pragma unroll
        for (int j = 0; j < 8; ++j) acc[i][j] = 0.0f;

    for (int k0 = 0; k0 < K; k0 += 16) {
        // load 128x16 tiles of A and B (float4 global, scalar smem stores)
#pragma unroll
        for (int s = 0; s < 2; ++s) {
            int f = tid + s * 256;            // 0..511
            int row = f >> 2;
            int c4 = (f & 3) << 2;
            float4 va = *reinterpret_cast<const float4*>(
                &A[(size_t)(bm + row) * K + k0 + c4]);
            sA[row * 17 + c4 + 0] = va.x;
            sA[row * 17 + c4 + 1] = va.y;
            sA[row * 17 + c4 + 2] = va.z;
            sA[row * 17 + c4 + 3] = va.w;
            float4 vb = *reinterpret_cast<const float4*>(
                &B[(size_t)(bn + row) * K + k0 + c4]);
            sB[row * 17 + c4 + 0] = vb.x;
            sB[row * 17 + c4 + 1] = vb.y;
            sB[row * 17 + c4 + 2] = vb.z;
            sB[row * 17 + c4 + 3] = vb.w;
        }
        __syncthreads();

#pragma unroll
        for (int kk = 0; kk < 16; ++kk) {
            float a[8], b[8];
#pragma unroll
            for (int i = 0; i < 8; ++i) a[i] = sA[(ty + 16 * i) * 17 + kk];
#pragma unroll
            for (int j = 0; j < 8; ++j) b[j] = sB[(tx + 16 * j) * 17 + kk];
#pragma unroll
            for (int i = 0; i < 8; ++i)
#pragma unroll
                for (int j = 0; j < 8; ++j) acc[i][j] += a[i] * b[j];
        }
        __syncthreads();
    }

    // epilogue
#pragma unroll
    for (int i = 0; i < 8; ++i) {
        int m = bm + ty + 16 * i;
#pragma unroll
        for (int j = 0; j < 8; ++j) {
            int n = bn + tx + 16 * j;
            float v = acc[i][j] + bias[n];
            if (EPI == 0) {
                int bidx = m >> 11;          // m / 2048
                int t = m & 2047;
                int h = n >> 6;
                int dh = n & 63;
                out[(((size_t)(bidx * NHEAD + h) * SEQ) + t) * HDIM + dh] = v;
            } else if (EPI == 1) {
                out[(size_t)m * N + n] = v + res[(size_t)m * N + n];
            } else { // GELU exact
                out[(size_t)m * N + n] =
                    0.5f * v * (1.0f + erff(v * 0.70710678118654752f));
            }
        }
    }
}

// ---------------- fused flash-style attention (fp32) ----------------------
// grid (BH=32, T/64=32), 256 threads. 64 queries x 32-key tiles, dh=64.
__global__ __launch_bounds__(256)
void attn_kernel(const float* __restrict__ Qg, const float* __restrict__ Kg,
                 const float* __restrict__ Vg, float* __restrict__ ctx) {
    __shared__ float sQt[64 * 64];   // transposed Q: [d][q]
    __shared__ float sKP[32 * 65];   // K tile [k][d] (pad 65); reused for P^T [k*64+q]
    __shared__ float sV[32 * 64];    // V tile [k][d]

    const int bh = blockIdx.x;           // b*8+h
    const int qt = blockIdx.y;
    const int b = bh >> 3;
    const int h = bh & 7;
    const int tid = threadIdx.x;
    const int tx = tid & 15;
    const int ty = tid >> 4;

    const float* Qb = Qg + ((size_t)bh * SEQ + qt * 64) * HDIM;
    const float* Kb = Kg + (size_t)bh * SEQ * HDIM;
    const float* Vb = Vg + (size_t)bh * SEQ * HDIM;

    // load Q tile transposed
    for (int idx = tid; idx < 64 * 64; idx += 256) {
        int q = idx >> 6, d = idx & 63;
        sQt[d * 64 + q] = Qb[idx];
    }

    float o[4][4];
    float mrow[4], lrow[4];
#pragma unroll
    for (int i = 0; i < 4; ++i) {
        mrow[i] = -1e30f;
        lrow[i] = 0.0f;
#pragma unroll
        for (int j = 0; j < 4; ++j) o[i][j] = 0.0f;
    }

    for (int kt = 0; kt < SEQ / 32; ++kt) {
        __syncthreads();   // previous iter done with sKP/sV (also covers Q load on iter 0)
        const float* Kt = Kb + kt * 32 * HDIM;
        const float* Vt = Vb + kt * 32 * HDIM;
        for (int idx = tid; idx < 32 * 64; idx += 256) {
            int k = idx >> 6, d = idx & 63;
            sKP[k * 65 + d] = Kt[idx];
            sV[k * 64 + d] = Vt[idx];
        }
        __syncthreads();

        // S = Q K^T, 64x32 tile, each thread 4x2
        float s[4][2] = {{0.f, 0.f}, {0.f, 0.f}, {0.f, 0.f}, {0.f, 0.f}};
#pragma unroll 8
        for (int d = 0; d < 64; ++d) {
            float a[4], bb[2];
#pragma unroll
            for (int i = 0; i < 4; ++i) a[i] = sQt[d * 64 + ty + 16 * i];
#pragma unroll
            for (int j = 0; j < 2; ++j) bb[j] = sKP[(tx + 16 * j) * 65 + d];
#pragma unroll
            for (int i = 0; i < 4; ++i)
#pragma unroll
                for (int j = 0; j < 2; ++j) s[i][j] += a[i] * bb[j];
        }

        // online softmax per query row (rows = ty+16i; 16 tx-lanes share a row)
        float p[4][2];
#pragma unroll
        for (int i = 0; i < 4; ++i) {
            float s0 = s[i][0] * 0.125f;   // 1/sqrt(64)
            float s1 = s[i][1] * 0.125f;
            float tmax = fmaxf(s0, s1);
#pragma unroll
            for (int off = 8; off; off >>= 1)
                tmax = fmaxf(tmax, __shfl_xor_sync(0xffffffffu, tmax, off));
            float mnew = fmaxf(mrow[i], tmax);
            float fac = __expf(mrow[i] - mnew);
            float p0 = __expf(s0 - mnew);
            float p1 = __expf(s1 - mnew);
            float rs = p0 + p1;
#pragma unroll
            for (int off = 8; off; off >>= 1)
                rs += __shfl_xor_sync(0xffffffffu, rs, off);
            lrow[i] = lrow[i] * fac + rs;
            mrow[i] = mnew;
#pragma unroll
            for (int j = 0; j < 4; ++j) o[i][j] *= fac;
            p[i][0] = p0;
            p[i][1] = p1;
        }

        __syncthreads();   // everyone done reading K tile
        // store P transposed into sKP region: [k*64 + q]
#pragma unroll
        for (int i = 0; i < 4; ++i)
#pragma unroll
            for (int j = 0; j < 2; ++j)
                sKP[(tx + 16 * j) * 64 + (ty + 16 * i)] = p[i][j];
        __syncthreads();

        // O += P * V  (32-deep)
#pragma unroll 8
        for (int kk = 0; kk < 32; ++kk) {
            float a[4], bb[4];
#pragma unroll
            for (int i = 0; i < 4; ++i) a[i] = sKP[kk * 64 + ty + 16 * i];
#pragma unroll
            for (int j = 0; j < 4; ++j) bb[j] = sV[kk * 64 + tx + 16 * j];
#pragma unroll
            for (int i = 0; i < 4; ++i)
#pragma unroll
                for (int j = 0; j < 4; ++j) o[i][j] += a[i] * bb[j];
        }
    }

    // write ctx in [B,T,D] layout
#pragma unroll
    for (int i = 0; i < 4; ++i) {
        float inv = 1.0f / lrow[i];
        int t = qt * 64 + ty + 16 * i;
#pragma unroll
        for (int j = 0; j < 4; ++j) {
            ctx[((size_t)(b * SEQ + t)) * DMODEL + h * HDIM + tx + 16 * j] =
                o[i][j] * inv;
        }
    }
}

// ---------------- LayerNorm: one block per row, 128 threads, D=512 --------
__global__ __launch_bounds__(128)
void ln_kernel(const float* __restrict__ in, const float* __restrict__ g,
               const float* __restrict__ beta, float* __restrict__ out) {
    __shared__ float red[8];
    const int row = blockIdx.x;
    const int tid = threadIdx.x;
    const int lane = tid & 31;
    const int wid = tid >> 5;

    float4 x4 = *reinterpret_cast<const float4*>(in + (size_t)row * DMODEL + tid * 4);
    float s = x4.x + x4.y + x4.z + x4.w;
#pragma unroll
    for (int off = 16; off; off >>= 1) s += __shfl_xor_sync(0xffffffffu, s, off);
    if (lane == 0) red[wid] = s;
    __syncthreads();
    float mean = (red[0] + red[1] + red[2] + red[3]) * (1.0f / DMODEL);

    float d0 = x4.x - mean, d1 = x4.y - mean, d2 = x4.z - mean, d3 = x4.w - mean;
    float sq = d0 * d0 + d1 * d1 + d2 * d2 + d3 * d3;
#pragma unroll
    for (int off = 16; off; off >>= 1) sq += __shfl_xor_sync(0xffffffffu, sq, off);
    if (lane == 0) red[4 + wid] = sq;
    __syncthreads();
    float var = (red[4] + red[5] + red[6] + red[7]) * (1.0f / DMODEL);
    float rstd = rsqrtf(var + 1e-5f);

    float4 g4 = *reinterpret_cast<const float4*>(g + tid * 4);
    float4 b4 = *reinterpret_cast<const float4*>(beta + tid * 4);
    float4 y;
    y.x = d0 * rstd * g4.x + b4.x;
    y.y = d1 * rstd * g4.y + b4.y;
    y.z = d2 * rstd * g4.z + b4.z;
    y.w = d3 * rstd * g4.w + b4.w;
    *reinterpret_cast<float4*>(out + (size_t)row * DMODEL + tid * 4) = y;
}

// ---------------- host-side orchestration ---------------------------------
extern "C" void kernel_launch(void* const* d_in, const int* in_sizes, int n_in,
                              void* d_out, int out_size) {
    const float* src = (const float*)d_in[0];
    const float* Wq = (const float*)d_in[1];
    const float* bq = (const float*)d_in[2];
    const float* Wk = (const float*)d_in[3];
    const float* bk = (const float*)d_in[4];
    const float* Wv = (const float*)d_in[5];
    const float* bv = (const float*)d_in[6];
    const float* Wo = (const float*)d_in[7];
    const float* bo = (const float*)d_in[8];
    const float* W1 = (const float*)d_in[9];
    const float* b1 = (const float*)d_in[10];
    const float* W2 = (const float*)d_in[11];
    const float* b2 = (const float*)d_in[12];
    const float* g1 = (const float*)d_in[13];
    const float* be1 = (const float*)d_in[14];
    const float* g2 = (const float*)d_in[15];
    const float* be2 = (const float*)d_in[16];
    float* outp = (float*)d_out;

    void *pq, *pk, *pv, *pctx, *ptmp, *px1, *ph;
    cudaGetSymbolAddress(&pq, g_q);
    cudaGetSymbolAddress(&pk, g_k);
    cudaGetSymbolAddress(&pv, g_v);
    cudaGetSymbolAddress(&pctx, g_ctx);
    cudaGetSymbolAddress(&ptmp, g_tmp);
    cudaGetSymbolAddress(&px1, g_x1);
    cudaGetSymbolAddress(&ph, g_h);
    float* Q = (float*)pq;
    float* K = (float*)pk;
    float* V = (float*)pv;
    float* CTX = (float*)pctx;
    float* TMP = (float*)ptmp;
    float* X1 = (float*)px1;
    float* HID = (float*)ph;

    dim3 blk(256);
    dim3 grid_d(DMODEL / 128, MROWS / 128);   // (4, 64)
    dim3 grid_ff(DFF / 128, MROWS / 128);     // (16, 64)

    // Q/K/V projections -> [BH, T, 64]
    gemm_kernel<0><<<grid_d, blk>>>(src, Wq, bq, nullptr, Q, MROWS, DMODEL, DMODEL);
    gemm_kernel<0><<<grid_d, blk>>>(src, Wk, bk, nullptr, K, MROWS, DMODEL, DMODEL);
    gemm_kernel<0><<<grid_d, blk>>>(src, Wv, bv, nullptr, V, MROWS, DMODEL, DMODEL);

    // attention -> ctx [B,T,D]
    attn_kernel<<<dim3(BATCH * NHEAD, SEQ / 64), blk>>>(Q, K, V, CTX);

    // O-proj + bias + residual(src) -> TMP ; LN1 -> X1
    gemm_kernel<1><<<grid_d, blk>>>(CTX, Wo, bo, src, TMP, MROWS, DMODEL, DMODEL);
    ln_kernel<<<MROWS, 128>>>(TMP, g1, be1, X1);

    // FFN1 + GELU -> HID
    gemm_kernel<2><<<grid_ff, blk>>>(X1, W1, b1, nullptr, HID, MROWS, DFF, DMODEL);

    // FFN2 + bias + residual(X1) -> TMP ; LN2 -> out
    gemm_kernel<1><<<grid_d, blk>>>(HID, W2, b2, X1, TMP, MROWS, DMODEL, DFF);
    ln_kernel<<<MROWS, 128>>>(TMP, g2, be2, outp);
}

// round 8
// speedup vs baseline: 1.4398x; 1.4398x over previous
#include <cuda_runtime.h>
#include <cuda_bf16.h>
#include <math.h>
#include <stdint.h>

// Problem constants
#define BATCH 4
#define SEQ   2048
#define DMODEL 512
#define NHEAD 8
#define HDIM  64
#define DFF   2048
#define MROWS (BATCH * SEQ)   // 8192

// ---------------- scratch (static device arrays; no allocation allowed) ----
__device__ float g_q[BATCH * NHEAD * SEQ * HDIM];   // [BH, T, 64]
__device__ float g_k[BATCH * NHEAD * SEQ * HDIM];
__device__ float g_v[BATCH * NHEAD * SEQ * HDIM];
__device__ float g_ctx[MROWS * DMODEL];             // [B,T,D]
__device__ float g_tmp[MROWS * DMODEL];             // pre-LN buffer (reused)
__device__ float g_x1[MROWS * DMODEL];              // post-LN1 (FFN input + residual2)
__device__ float g_h[MROWS * DFF];                  // FFN hidden

// ================= bf16-split tensor-core GEMM =============================
// C = A (MxK) * B^T (B is NxK row-major), fp32 in/out.
// Each operand x is split x = hi + lo (both bf16); product uses 3 MMAs
// (hi*hi + hi*lo + lo*hi), fp32 accumulate -> ~1e-5 accuracy.
// Block tile 128x128, BK=32, 256 threads (8 warps as 2m x 4n, warp tile 64x32).
// EPI 0: heads scatter + bias     EPI 1: bias + residual   EPI 2: bias + GELU

#define LDK 40   // padded row length in bf16 elements (80B stride: conflict-free ldmatrix)

__device__ __forceinline__ uint32_t smem_u32(const void* p) {
    return (uint32_t)__cvta_generic_to_shared(p);
}

__device__ __forceinline__ void ldmx4(uint32_t addr, uint32_t& r0, uint32_t& r1,
                                      uint32_t& r2, uint32_t& r3) {
    asm volatile("ldmatrix.sync.aligned.m8n8.x4.shared.b16 {%0,%1,%2,%3}, [%4];"
                 : "=r"(r0), "=r"(r1), "=r"(r2), "=r"(r3) : "r"(addr));
}

__device__ __forceinline__ void mma_bf16(float* c, const uint32_t* a, const uint32_t* b) {
    asm volatile(
        "mma.sync.aligned.m16n8k16.row.col.f32.bf16.bf16.f32 "
        "{%0,%1,%2,%3}, {%4,%5,%6,%7}, {%8,%9}, {%0,%1,%2,%3};"
        : "+f"(c[0]), "+f"(c[1]), "+f"(c[2]), "+f"(c[3])
        : "r"(a[0]), "r"(a[1]), "r"(a[2]), "r"(a[3]), "r"(b[0]), "r"(b[1]));
}

template <int EPI>
__global__ __launch_bounds__(256)
void gemm_mma(const float* __restrict__ A, const float* __restrict__ B,
              const float* __restrict__ bias, const float* __restrict__ res,
              float* __restrict__ out, int M, int N, int K) {
    __shared__ __nv_bfloat16 sAh[128 * LDK];
    __shared__ __nv_bfloat16 sAl[128 * LDK];
    __shared__ __nv_bfloat16 sBh[128 * LDK];
    __shared__ __nv_bfloat16 sBl[128 * LDK];

    const int tid = threadIdx.x;
    const int warp = tid >> 5;
    const int lane = tid & 31;
    const int wm = (warp & 1) * 64;     // warp m-offset within block
    const int wn = (warp >> 1) * 32;    // warp n-offset
    const int bm = blockIdx.y * 128;
    const int bn = blockIdx.x * 128;

    float acc[4][4][4];                 // [am][an][c]
#pragma unroll
    for (int i = 0; i < 4; ++i)
#pragma unroll
        for (int j = 0; j < 4; ++j)
#pragma unroll
            for (int c = 0; c < 4; ++c) acc[i][j][c] = 0.0f;

    // per-lane ldmatrix source rows (computed once)
    const int mat = lane >> 3;          // 0..3
    const int mrw = lane & 7;           // row within 8x8 matrix

    for (int k0 = 0; k0 < K; k0 += 32) {
        // ---- load 128x32 fp32 tiles of A and B, split to bf16 hi/lo ----
#pragma unroll
        for (int it = 0; it < 4; ++it) {
            int idx = it * 256 + tid;       // 1024 float4 slots
            int row = idx >> 3;
            int col = (idx & 7) << 2;       // 0..28
            float4 a = *reinterpret_cast<const float4*>(
                &A[(size_t)(bm + row) * K + k0 + col]);
            float4 b = *reinterpret_cast<const float4*>(
                &B[(size_t)(bn + row) * K + k0 + col]);
            float av[4] = {a.x, a.y, a.z, a.w};
            float bv[4] = {b.x, b.y, b.z, b.w};
            __nv_bfloat16 ah[4], al[4], bh[4], bl[4];
#pragma unroll
            for (int e = 0; e < 4; ++e) {
                ah[e] = __float2bfloat16_rn(av[e]);
                al[e] = __float2bfloat16_rn(av[e] - __bfloat162float(ah[e]));
                bh[e] = __float2bfloat16_rn(bv[e]);
                bl[e] = __float2bfloat16_rn(bv[e] - __bfloat162float(bh[e]));
            }
            int so = row * LDK + col;
            *reinterpret_cast<__nv_bfloat162*>(&sAh[so])     = __nv_bfloat162(ah[0], ah[1]);
            *reinterpret_cast<__nv_bfloat162*>(&sAh[so + 2]) = __nv_bfloat162(ah[2], ah[3]);
            *reinterpret_cast<__nv_bfloat162*>(&sAl[so])     = __nv_bfloat162(al[0], al[1]);
            *reinterpret_cast<__nv_bfloat162*>(&sAl[so + 2]) = __nv_bfloat162(al[2], al[3]);
            *reinterpret_cast<__nv_bfloat162*>(&sBh[so])     = __nv_bfloat162(bh[0], bh[1]);
            *reinterpret_cast<__nv_bfloat162*>(&sBh[so + 2]) = __nv_bfloat162(bh[2], bh[3]);
            *reinterpret_cast<__nv_bfloat162*>(&sBl[so])     = __nv_bfloat162(bl[0], bl[1]);
            *reinterpret_cast<__nv_bfloat162*>(&sBl[so + 2]) = __nv_bfloat162(bl[2], bl[3]);
        }
        __syncthreads();

        // ---- two k16 steps ----
#pragma unroll
        for (int ks = 0; ks < 32; ks += 16) {
            // B fragments for all 4 n-atoms (two x4 loads per hi/lo)
            uint32_t bhF[4][2], blF[4][2];
#pragma unroll
            for (int pair = 0; pair < 2; ++pair) {
                // matrices: (atom,k0),(atom,k8),(atom+1,k0),(atom+1,k8)
                int atom = pair * 2 + (mat >> 1);
                int kc = ks + (mat & 1) * 8;
                int nrow = wn + atom * 8 + mrw;
                uint32_t adrH = smem_u32(&sBh[nrow * LDK + kc]);
                uint32_t adrL = smem_u32(&sBl[nrow * LDK + kc]);
                uint32_t r0, r1, r2, r3;
                ldmx4(adrH, r0, r1, r2, r3);
                bhF[pair * 2][0] = r0; bhF[pair * 2][1] = r1;
                bhF[pair * 2 + 1][0] = r2; bhF[pair * 2 + 1][1] = r3;
                ldmx4(adrL, r0, r1, r2, r3);
                blF[pair * 2][0] = r0; blF[pair * 2][1] = r1;
                blF[pair * 2 + 1][0] = r2; blF[pair * 2 + 1][1] = r3;
            }
            // A fragments per m-atom, then 3 MMAs against each n-atom
#pragma unroll
            for (int am = 0; am < 4; ++am) {
                int arow = wm + am * 16 + (mat & 1) * 8 + mrw;
                int akc = ks + (mat >> 1) * 8;
                uint32_t ahF[4], alF[4];
                ldmx4(smem_u32(&sAh[arow * LDK + akc]), ahF[0], ahF[1], ahF[2], ahF[3]);
                ldmx4(smem_u32(&sAl[arow * LDK + akc]), alF[0], alF[1], alF[2], alF[3]);
#pragma unroll
                for (int an = 0; an < 4; ++an) {
                    mma_bf16(acc[am][an], ahF, bhF[an]);
                    mma_bf16(acc[am][an], ahF, blF[an]);
                    mma_bf16(acc[am][an], alF, bhF[an]);
                }
            }
        }
        __syncthreads();
    }

    // ---- epilogue ----
    const int gid = lane >> 2;   // row group 0..7
    const int tig = lane & 3;    // col pair 0..3
#pragma unroll
    for (int am = 0; am < 4; ++am) {
#pragma unroll
        for (int an = 0; an < 4; ++an) {
#pragma unroll
            for (int c = 0; c < 4; ++c) {
                int m = bm + wm + am * 16 + gid + ((c >> 1) ? 8 : 0);
                int n = bn + wn + an * 8 + tig * 2 + (c & 1);
                float v = acc[am][an][c] + bias[n];
                if (EPI == 0) {
                    int bidx = m >> 11;          // m / 2048
                    int t = m & 2047;
                    int h = n >> 6;
                    int dh = n & 63;
                    out[(((size_t)(bidx * NHEAD + h) * SEQ) + t) * HDIM + dh] = v;
                } else if (EPI == 1) {
                    out[(size_t)m * N + n] = v + res[(size_t)m * N + n];
                } else {
                    out[(size_t)m * N + n] =
                        0.5f * v * (1.0f + erff(v * 0.70710678118654752f));
                }
            }
        }
    }
}

// ---------------- fused flash-style attention (fp32) ----------------------
// grid (BH=32, T/64=32), 256 threads. 64 queries x 32-key tiles, dh=64.
__global__ __launch_bounds__(256)
void attn_kernel(const float* __restrict__ Qg, const float* __restrict__ Kg,
                 const float* __restrict__ Vg, float* __restrict__ ctx) {
    __shared__ float sQt[64 * 64];   // transposed Q: [d][q]
    __shared__ float sKP[32 * 65];   // K tile [k][d] (pad 65); reused for P^T [k*64+q]
    __shared__ float sV[32 * 64];    // V tile [k][d]

    const int bh = blockIdx.x;           // b*8+h
    const int qt = blockIdx.y;
    const int b = bh >> 3;
    const int h = bh & 7;
    const int tid = threadIdx.x;
    const int tx = tid & 15;
    const int ty = tid >> 4;

    const float* Qb = Qg + ((size_t)bh * SEQ + qt * 64) * HDIM;
    const float* Kb = Kg + (size_t)bh * SEQ * HDIM;
    const float* Vb = Vg + (size_t)bh * SEQ * HDIM;

    for (int idx = tid; idx < 64 * 64; idx += 256) {
        int q = idx >> 6, d = idx & 63;
        sQt[d * 64 + q] = Qb[idx];
    }

    float o[4][4];
    float mrow[4], lrow[4];
#pragma unroll
    for (int i = 0; i < 4; ++i) {
        mrow[i] = -1e30f;
        lrow[i] = 0.0f;
#pragma unroll
        for (int j = 0; j < 4; ++j) o[i][j] = 0.0f;
    }

    for (int kt = 0; kt < SEQ / 32; ++kt) {
        __syncthreads();
        const float* Kt = Kb + kt * 32 * HDIM;
        const float* Vt = Vb + kt * 32 * HDIM;
        for (int idx = tid; idx < 32 * 64; idx += 256) {
            int k = idx >> 6, d = idx & 63;
            sKP[k * 65 + d] = Kt[idx];
            sV[k * 64 + d] = Vt[idx];
        }
        __syncthreads();

        float s[4][2] = {{0.f, 0.f}, {0.f, 0.f}, {0.f, 0.f}, {0.f, 0.f}};
#pragma unroll 8
        for (int d = 0; d < 64; ++d) {
            float a[4], bb[2];
#pragma unroll
            for (int i = 0; i < 4; ++i) a[i] = sQt[d * 64 + ty + 16 * i];
#pragma unroll
            for (int j = 0; j < 2; ++j) bb[j] = sKP[(tx + 16 * j) * 65 + d];
#pragma unroll
            for (int i = 0; i < 4; ++i)
#pragma unroll
                for (int j = 0; j < 2; ++j) s[i][j] += a[i] * bb[j];
        }

        float p[4][2];
#pragma unroll
        for (int i = 0; i < 4; ++i) {
            float s0 = s[i][0] * 0.125f;
            float s1 = s[i][1] * 0.125f;
            float tmax = fmaxf(s0, s1);
#pragma unroll
            for (int off = 8; off; off >>= 1)
                tmax = fmaxf(tmax, __shfl_xor_sync(0xffffffffu, tmax, off));
            float mnew = fmaxf(mrow[i], tmax);
            float fac = __expf(mrow[i] - mnew);
            float p0 = __expf(s0 - mnew);
            float p1 = __expf(s1 - mnew);
            float rs = p0 + p1;
#pragma unroll
            for (int off = 8; off; off >>= 1)
                rs += __shfl_xor_sync(0xffffffffu, rs, off);
            lrow[i] = lrow[i] * fac + rs;
            mrow[i] = mnew;
#pragma unroll
            for (int j = 0; j < 4; ++j) o[i][j] *= fac;
            p[i][0] = p0;
            p[i][1] = p1;
        }

        __syncthreads();
#pragma unroll
        for (int i = 0; i < 4; ++i)
#pragma unroll
            for (int j = 0; j < 2; ++j)
                sKP[(tx + 16 * j) * 64 + (ty + 16 * i)] = p[i][j];
        __syncthreads();

#pragma unroll 8
        for (int kk = 0; kk < 32; ++kk) {
            float a[4], bb[4];
#pragma unroll
            for (int i = 0; i < 4; ++i) a[i] = sKP[kk * 64 + ty + 16 * i];
#pragma unroll
            for (int j = 0; j < 4; ++j) bb[j] = sV[kk * 64 + tx + 16 * j];
#pragma unroll
            for (int i = 0; i < 4; ++i)
#pragma unroll
                for (int j = 0; j < 4; ++j) o[i][j] += a[i] * bb[j];
        }
    }

#pragma unroll
    for (int i = 0; i < 4; ++i) {
        float inv = 1.0f / lrow[i];
        int t = qt * 64 + ty + 16 * i;
#pragma unroll
        for (int j = 0; j < 4; ++j) {
            ctx[((size_t)(b * SEQ + t)) * DMODEL + h * HDIM + tx + 16 * j] =
                o[i][j] * inv;
        }
    }
}

// ---------------- LayerNorm: one block per row, 128 threads, D=512 --------
__global__ __launch_bounds__(128)
void ln_kernel(const float* __restrict__ in, const float* __restrict__ g,
               const float* __restrict__ beta, float* __restrict__ out) {
    __shared__ float red[8];
    const int row = blockIdx.x;
    const int tid = threadIdx.x;
    const int lane = tid & 31;
    const int wid = tid >> 5;

    float4 x4 = *reinterpret_cast<const float4*>(in + (size_t)row * DMODEL + tid * 4);
    float s = x4.x + x4.y + x4.z + x4.w;
#pragma unroll
    for (int off = 16; off; off >>= 1) s += __shfl_xor_sync(0xffffffffu, s, off);
    if (lane == 0) red[wid] = s;
    __syncthreads();
    float mean = (red[0] + red[1] + red[2] + red[3]) * (1.0f / DMODEL);

    float d0 = x4.x - mean, d1 = x4.y - mean, d2 = x4.z - mean, d3 = x4.w - mean;
    float sq = d0 * d0 + d1 * d1 + d2 * d2 + d3 * d3;
#pragma unroll
    for (int off = 16; off; off >>= 1) sq += __shfl_xor_sync(0xffffffffu, sq, off);
    if (lane == 0) red[4 + wid] = sq;
    __syncthreads();
    float var = (red[4] + red[5] + red[6] + red[7]) * (1.0f / DMODEL);
    float rstd = rsqrtf(var + 1e-5f);

    float4 g4 = *reinterpret_cast<const float4*>(g + tid * 4);
    float4 b4 = *reinterpret_cast<const float4*>(beta + tid * 4);
    float4 y;
    y.x = d0 * rstd * g4.x + b4.x;
    y.y = d1 * rstd * g4.y + b4.y;
    y.z = d2 * rstd * g4.z + b4.z;
    y.w = d3 * rstd * g4.w + b4.w;
    *reinterpret_cast<float4*>(out + (size_t)row * DMODEL + tid * 4) = y;
}

// ---------------- host-side orchestration ---------------------------------
extern "C" void kernel_launch(void* const* d_in, const int* in_sizes, int n_in,
                              void* d_out, int out_size) {
    const float* src = (const float*)d_in[0];
    const float* Wq = (const float*)d_in[1];
    const float* bq = (const float*)d_in[2];
    const float* Wk = (const float*)d_in[3];
    const float* bk = (const float*)d_in[4];
    const float* Wv = (const float*)d_in[5];
    const float* bv = (const float*)d_in[6];
    const float* Wo = (const float*)d_in[7];
    const float* bo = (const float*)d_in[8];
    const float* W1 = (const float*)d_in[9];
    const float* b1 = (const float*)d_in[10];
    const float* W2 = (const float*)d_in[11];
    const float* b2 = (const float*)d_in[12];
    const float* g1 = (const float*)d_in[13];
    const float* be1 = (const float*)d_in[14];
    const float* g2 = (const float*)d_in[15];
    const float* be2 = (const float*)d_in[16];
    float* outp = (float*)d_out;

    void *pq, *pk, *pv, *pctx, *ptmp, *px1, *ph;
    cudaGetSymbolAddress(&pq, g_q);
    cudaGetSymbolAddress(&pk, g_k);
    cudaGetSymbolAddress(&pv, g_v);
    cudaGetSymbolAddress(&pctx, g_ctx);
    cudaGetSymbolAddress(&ptmp, g_tmp);
    cudaGetSymbolAddress(&px1, g_x1);
    cudaGetSymbolAddress(&ph, g_h);
    float* Q = (float*)pq;
    float* K = (float*)pk;
    float* V = (float*)pv;
    float* CTX = (float*)pctx;
    float* TMP = (float*)ptmp;
    float* X1 = (float*)px1;
    float* HID = (float*)ph;

    dim3 blk(256);
    dim3 grid_d(DMODEL / 128, MROWS / 128);   // (4, 64)
    dim3 grid_ff(DFF / 128, MROWS / 128);     // (16, 64)

    // Q/K/V projections -> [BH, T, 64]
    gemm_mma<0><<<grid_d, blk>>>(src, Wq, bq, nullptr, Q, MROWS, DMODEL, DMODEL);
    gemm_mma<0><<<grid_d, blk>>>(src, Wk, bk, nullptr, K, MROWS, DMODEL, DMODEL);
    gemm_mma<0><<<grid_d, blk>>>(src, Wv, bv, nullptr, V, MROWS, DMODEL, DMODEL);

    // attention -> ctx [B,T,D]
    attn_kernel<<<dim3(BATCH * NHEAD, SEQ / 64), blk>>>(Q, K, V, CTX);

    // O-proj + bias + residual(src) -> TMP ; LN1 -> X1
    gemm_mma<1><<<grid_d, blk>>>(CTX, Wo, bo, src, TMP, MROWS, DMODEL, DMODEL);
    ln_kernel<<<MROWS, 128>>>(TMP, g1, be1, X1);

    // FFN1 + GELU -> HID
    gemm_mma<2><<<grid_ff, blk>>>(X1, W1, b1, nullptr, HID, MROWS, DFF, DMODEL);

    // FFN2 + bias + residual(X1) -> TMP ; LN2 -> out
    gemm_mma<1><<<grid_d, blk>>>(HID, W2, b2, X1, TMP, MROWS, DMODEL, DFF);
    ln_kernel<<<MROWS, 128>>>(TMP, g2, be2, outp);
}

// round 10
// speedup vs baseline: 2.0764x; 1.4422x over previous
#include <cuda_runtime.h>
#include <cuda_bf16.h>
#include <math.h>
#include <stdint.h>

// Problem constants
#define BATCH 4
#define SEQ   2048
#define DMODEL 512
#define NHEAD 8
#define HDIM  64
#define DFF   2048
#define MROWS (BATCH * SEQ)   // 8192

// ---------------- scratch (static device arrays; no allocation allowed) ----
__device__ float g_q[BATCH * NHEAD * SEQ * HDIM];   // [BH, T, 64]
__device__ float g_k[BATCH * NHEAD * SEQ * HDIM];
__device__ float g_v[BATCH * NHEAD * SEQ * HDIM];
__device__ float g_ctx[MROWS * DMODEL];             // [B,T,D]
__device__ float g_tmp[MROWS * DMODEL];             // pre-LN buffer (reused)
__device__ float g_x1[MROWS * DMODEL];              // post-LN1 (FFN input + residual2)
__device__ float g_h[MROWS * DFF];                  // FFN hidden

// ---------------- common mma helpers ---------------------------------------
__device__ __forceinline__ uint32_t smem_u32(const void* p) {
    return (uint32_t)__cvta_generic_to_shared(p);
}

__device__ __forceinline__ void ldmx4(uint32_t addr, uint32_t& r0, uint32_t& r1,
                                      uint32_t& r2, uint32_t& r3) {
    asm volatile("ldmatrix.sync.aligned.m8n8.x4.shared.b16 {%0,%1,%2,%3}, [%4];"
                 : "=r"(r0), "=r"(r1), "=r"(r2), "=r"(r3) : "r"(addr));
}

__device__ __forceinline__ void mma_bf16(float* c, const uint32_t* a, const uint32_t* b) {
    asm volatile(
        "mma.sync.aligned.m16n8k16.row.col.f32.bf16.bf16.f32 "
        "{%0,%1,%2,%3}, {%4,%5,%6,%7}, {%8,%9}, {%0,%1,%2,%3};"
        : "+f"(c[0]), "+f"(c[1]), "+f"(c[2]), "+f"(c[3])
        : "r"(a[0]), "r"(a[1]), "r"(a[2]), "r"(a[3]), "r"(b[0]), "r"(b[1]));
}

// split (x,y) into packed bf16x2 hi and lo words
__device__ __forceinline__ void split2(float x, float y, uint32_t& hi, uint32_t& lo) {
    __nv_bfloat16 xh = __float2bfloat16_rn(x);
    __nv_bfloat16 yh = __float2bfloat16_rn(y);
    __nv_bfloat16 xl = __float2bfloat16_rn(x - __bfloat162float(xh));
    __nv_bfloat16 yl = __float2bfloat16_rn(y - __bfloat162float(yh));
    __nv_bfloat162 h2(xh, yh), l2(xl, yl);
    hi = *reinterpret_cast<uint32_t*>(&h2);
    lo = *reinterpret_cast<uint32_t*>(&l2);
}

// ================= bf16-split tensor-core GEMM =============================
#define LDK 40   // padded row length in bf16 elements (80B stride)

template <int EPI>
__global__ __launch_bounds__(256)
void gemm_mma(const float* __restrict__ A, const float* __restrict__ B,
              const float* __restrict__ bias, const float* __restrict__ res,
              float* __restrict__ out, int M, int N, int K) {
    __shared__ __nv_bfloat16 sAh[128 * LDK];
    __shared__ __nv_bfloat16 sAl[128 * LDK];
    __shared__ __nv_bfloat16 sBh[128 * LDK];
    __shared__ __nv_bfloat16 sBl[128 * LDK];

    const int tid = threadIdx.x;
    const int warp = tid >> 5;
    const int lane = tid & 31;
    const int wm = (warp & 1) * 64;
    const int wn = (warp >> 1) * 32;
    const int bm = blockIdx.y * 128;
    const int bn = blockIdx.x * 128;

    float acc[4][4][4];
#pragma unroll
    for (int i = 0; i < 4; ++i)
#pragma unroll
        for (int j = 0; j < 4; ++j)
#pragma unroll
            for (int c = 0; c < 4; ++c) acc[i][j][c] = 0.0f;

    const int mat = lane >> 3;
    const int mrw = lane & 7;

    for (int k0 = 0; k0 < K; k0 += 32) {
#pragma unroll
        for (int it = 0; it < 4; ++it) {
            int idx = it * 256 + tid;
            int row = idx >> 3;
            int col = (idx & 7) << 2;
            float4 a = *reinterpret_cast<const float4*>(
                &A[(size_t)(bm + row) * K + k0 + col]);
            float4 b = *reinterpret_cast<const float4*>(
                &B[(size_t)(bn + row) * K + k0 + col]);
            int so = row * LDK + col;
            uint32_t h0, l0, h1, l1;
            split2(a.x, a.y, h0, l0);
            split2(a.z, a.w, h1, l1);
            *reinterpret_cast<uint32_t*>(&sAh[so])     = h0;
            *reinterpret_cast<uint32_t*>(&sAh[so + 2]) = h1;
            *reinterpret_cast<uint32_t*>(&sAl[so])     = l0;
            *reinterpret_cast<uint32_t*>(&sAl[so + 2]) = l1;
            split2(b.x, b.y, h0, l0);
            split2(b.z, b.w, h1, l1);
            *reinterpret_cast<uint32_t*>(&sBh[so])     = h0;
            *reinterpret_cast<uint32_t*>(&sBh[so + 2]) = h1;
            *reinterpret_cast<uint32_t*>(&sBl[so])     = l0;
            *reinterpret_cast<uint32_t*>(&sBl[so + 2]) = l1;
        }
        __syncthreads();

#pragma unroll
        for (int ks = 0; ks < 32; ks += 16) {
            uint32_t bhF[4][2], blF[4][2];
#pragma unroll
            for (int pair = 0; pair < 2; ++pair) {
                int atom = pair * 2 + (mat >> 1);
                int kc = ks + (mat & 1) * 8;
                int nrow = wn + atom * 8 + mrw;
                uint32_t adrH = smem_u32(&sBh[nrow * LDK + kc]);
                uint32_t adrL = smem_u32(&sBl[nrow * LDK + kc]);
                uint32_t r0, r1, r2, r3;
                ldmx4(adrH, r0, r1, r2, r3);
                bhF[pair * 2][0] = r0; bhF[pair * 2][1] = r1;
                bhF[pair * 2 + 1][0] = r2; bhF[pair * 2 + 1][1] = r3;
                ldmx4(adrL, r0, r1, r2, r3);
                blF[pair * 2][0] = r0; blF[pair * 2][1] = r1;
                blF[pair * 2 + 1][0] = r2; blF[pair * 2 + 1][1] = r3;
            }
#pragma unroll
            for (int am = 0; am < 4; ++am) {
                int arow = wm + am * 16 + (mat & 1) * 8 + mrw;
                int akc = ks + (mat >> 1) * 8;
                uint32_t ahF[4], alF[4];
                ldmx4(smem_u32(&sAh[arow * LDK + akc]), ahF[0], ahF[1], ahF[2], ahF[3]);
                ldmx4(smem_u32(&sAl[arow * LDK + akc]), alF[0], alF[1], alF[2], alF[3]);
#pragma unroll
                for (int an = 0; an < 4; ++an) {
                    mma_bf16(acc[am][an], ahF, bhF[an]);
                    mma_bf16(acc[am][an], ahF, blF[an]);
                    mma_bf16(acc[am][an], alF, bhF[an]);
                }
            }
        }
        __syncthreads();
    }

    const int gid = lane >> 2;
    const int tig = lane & 3;
#pragma unroll
    for (int am = 0; am < 4; ++am) {
#pragma unroll
        for (int an = 0; an < 4; ++an) {
#pragma unroll
            for (int c = 0; c < 4; ++c) {
                int m = bm + wm + am * 16 + gid + ((c >> 1) ? 8 : 0);
                int n = bn + wn + an * 8 + tig * 2 + (c & 1);
                float v = acc[am][an][c] + bias[n];
                if (EPI == 0) {
                    int bidx = m >> 11;
                    int t = m & 2047;
                    int h = n >> 6;
                    int dh = n & 63;
                    out[(((size_t)(bidx * NHEAD + h) * SEQ) + t) * HDIM + dh] = v;
                } else if (EPI == 1) {
                    out[(size_t)m * N + n] = v + res[(size_t)m * N + n];
                } else {
                    out[(size_t)m * N + n] =
                        0.5f * v * (1.0f + erff(v * 0.70710678118654752f));
                }
            }
        }
    }
}

// ================= tensor-core flash attention (split bf16) ================
// grid (BH=32, SEQ/128=16), 256 threads (8 warps). Each warp: 16 q rows.
// k-tiles of 64 keys. S and P stay in registers (FA2 fragment reuse).
#define ALD 72   // padded row length (144B stride) for conflict-free ldmatrix

#define ATTN_SMEM ((2 * 128 + 4 * 64) * ALD * 2)   // 73728 bytes

__global__ __launch_bounds__(256, 2)
void attn_mma(const float* __restrict__ Qg, const float* __restrict__ Kg,
              const float* __restrict__ Vg, float* __restrict__ ctx) {
    extern __shared__ __nv_bfloat16 sm[];
    __nv_bfloat16* sQh = sm;                     // [128][ALD]
    __nv_bfloat16* sQl = sQh + 128 * ALD;
    __nv_bfloat16* sKh = sQl + 128 * ALD;        // [64][ALD]   (k-major)
    __nv_bfloat16* sKl = sKh + 64 * ALD;
    __nv_bfloat16* sVh = sKl + 64 * ALD;         // [64][ALD]   V^T: [d][kk]
    __nv_bfloat16* sVl = sVh + 64 * ALD;

    const int bh = blockIdx.x;
    const int qt = blockIdx.y;
    const int b = bh >> 3;
    const int h = bh & 7;
    const int tid = threadIdx.x;
    const int warp = tid >> 5;
    const int lane = tid & 31;
    const int mat = lane >> 3;
    const int mrw = lane & 7;
    const int gid = lane >> 2;
    const int tig = lane & 3;

    const float* Qb = Qg + ((size_t)bh * SEQ + qt * 128) * HDIM;
    const float* Kb = Kg + (size_t)bh * SEQ * HDIM;
    const float* Vb = Vg + (size_t)bh * SEQ * HDIM;

    // ---- load Q tile 128x64, split into hi/lo ----
#pragma unroll
    for (int it = 0; it < 8; ++it) {
        int idx = it * 256 + tid;
        int row = idx >> 4;
        int col = (idx & 15) << 2;
        float4 q = *reinterpret_cast<const float4*>(&Qb[row * HDIM + col]);
        uint32_t h0, l0, h1, l1;
        split2(q.x, q.y, h0, l0);
        split2(q.z, q.w, h1, l1);
        int so = row * ALD + col;
        *reinterpret_cast<uint32_t*>(&sQh[so])     = h0;
        *reinterpret_cast<uint32_t*>(&sQh[so + 2]) = h1;
        *reinterpret_cast<uint32_t*>(&sQl[so])     = l0;
        *reinterpret_cast<uint32_t*>(&sQl[so + 2]) = l1;
    }

    float o[8][4];
#pragma unroll
    for (int j = 0; j < 8; ++j)
#pragma unroll
        for (int c = 0; c < 4; ++c) o[j][c] = 0.0f;
    float m0 = -1e30f, m1 = -1e30f, l0r = 0.0f, l1r = 0.0f;

    for (int kt = 0; kt < SEQ / 64; ++kt) {
        __syncthreads();   // previous iteration done with K/V smem (covers Q on iter 0)
        const float* Kt = Kb + kt * 64 * HDIM;
        const float* Vt = Vb + kt * 64 * HDIM;
#pragma unroll
        for (int it = 0; it < 4; ++it) {
            int idx = it * 256 + tid;
            int row = idx >> 4;            // kk
            int col = (idx & 15) << 2;     // d
            float4 k4 = *reinterpret_cast<const float4*>(&Kt[row * HDIM + col]);
            uint32_t h0, l0, h1, l1;
            split2(k4.x, k4.y, h0, l0);
            split2(k4.z, k4.w, h1, l1);
            int so = row * ALD + col;
            *reinterpret_cast<uint32_t*>(&sKh[so])     = h0;
            *reinterpret_cast<uint32_t*>(&sKh[so + 2]) = h1;
            *reinterpret_cast<uint32_t*>(&sKl[so])     = l0;
            *reinterpret_cast<uint32_t*>(&sKl[so + 2]) = l1;
            float4 v4 = *reinterpret_cast<const float4*>(&Vt[row * HDIM + col]);
            float vv[4] = {v4.x, v4.y, v4.z, v4.w};
#pragma unroll
            for (int e = 0; e < 4; ++e) {
                __nv_bfloat16 vh = __float2bfloat16_rn(vv[e]);
                __nv_bfloat16 vl = __float2bfloat16_rn(vv[e] - __bfloat162float(vh));
                sVh[(col + e) * ALD + row] = vh;   // transposed: [d][kk]
                sVl[(col + e) * ALD + row] = vl;
            }
        }
        __syncthreads();

        // ---- S = Q K^T : warp computes 16x64 ----
        float sa[8][4];
#pragma unroll
        for (int j = 0; j < 8; ++j)
#pragma unroll
            for (int c = 0; c < 4; ++c) sa[j][c] = 0.0f;

#pragma unroll
        for (int s = 0; s < 4; ++s) {
            int akc = 16 * s + (mat >> 1) * 8;
            int arow = 16 * warp + (mat & 1) * 8 + mrw;
            uint32_t qhF[4], qlF[4];
            ldmx4(smem_u32(&sQh[arow * ALD + akc]), qhF[0], qhF[1], qhF[2], qhF[3]);
            ldmx4(smem_u32(&sQl[arow * ALD + akc]), qlF[0], qlF[1], qlF[2], qlF[3]);
            uint32_t khF[8][2], klF[8][2];
#pragma unroll
            for (int pair = 0; pair < 4; ++pair) {
                int atom = pair * 2 + (mat >> 1);
                int kc = 16 * s + (mat & 1) * 8;
                int nrow = atom * 8 + mrw;
                uint32_t r0, r1, r2, r3;
                ldmx4(smem_u32(&sKh[nrow * ALD + kc]), r0, r1, r2, r3);
                khF[pair * 2][0] = r0; khF[pair * 2][1] = r1;
                khF[pair * 2 + 1][0] = r2; khF[pair * 2 + 1][1] = r3;
                ldmx4(smem_u32(&sKl[nrow * ALD + kc]), r0, r1, r2, r3);
                klF[pair * 2][0] = r0; klF[pair * 2][1] = r1;
                klF[pair * 2 + 1][0] = r2; klF[pair * 2 + 1][1] = r3;
            }
#pragma unroll
            for (int j = 0; j < 8; ++j) {
                mma_bf16(sa[j], qhF, khF[j]);
                mma_bf16(sa[j], qhF, klF[j]);
                mma_bf16(sa[j], qlF, khF[j]);
            }
        }

        // ---- online softmax (rows gid and gid+8; quad shfl reductions) ----
        float mx0 = -1e30f, mx1 = -1e30f;
#pragma unroll
        for (int j = 0; j < 8; ++j) {
            sa[j][0] *= 0.125f; sa[j][1] *= 0.125f;
            sa[j][2] *= 0.125f; sa[j][3] *= 0.125f;
            mx0 = fmaxf(mx0, fmaxf(sa[j][0], sa[j][1]));
            mx1 = fmaxf(mx1, fmaxf(sa[j][2], sa[j][3]));
        }
        mx0 = fmaxf(mx0, __shfl_xor_sync(0xffffffffu, mx0, 1));
        mx0 = fmaxf(mx0, __shfl_xor_sync(0xffffffffu, mx0, 2));
        mx1 = fmaxf(mx1, __shfl_xor_sync(0xffffffffu, mx1, 1));
        mx1 = fmaxf(mx1, __shfl_xor_sync(0xffffffffu, mx1, 2));
        float mn0 = fmaxf(m0, mx0), mn1 = fmaxf(m1, mx1);
        float f0 = __expf(m0 - mn0), f1 = __expf(m1 - mn1);

        float rs0 = 0.0f, rs1 = 0.0f;
        uint32_t ph2[8][2], pl2[8][2];
#pragma unroll
        for (int j = 0; j < 8; ++j) {
            float p0 = __expf(sa[j][0] - mn0);
            float p1 = __expf(sa[j][1] - mn0);
            float p2 = __expf(sa[j][2] - mn1);
            float p3 = __expf(sa[j][3] - mn1);
            rs0 += p0 + p1;
            rs1 += p2 + p3;
            split2(p0, p1, ph2[j][0], pl2[j][0]);
            split2(p2, p3, ph2[j][1], pl2[j][1]);
            o[j][0] *= f0; o[j][1] *= f0;
            o[j][2] *= f1; o[j][3] *= f1;
        }
        rs0 += __shfl_xor_sync(0xffffffffu, rs0, 1);
        rs0 += __shfl_xor_sync(0xffffffffu, rs0, 2);
        rs1 += __shfl_xor_sync(0xffffffffu, rs1, 1);
        rs1 += __shfl_xor_sync(0xffffffffu, rs1, 2);
        l0r = l0r * f0 + rs0;
        l1r = l1r * f1 + rs1;
        m0 = mn0; m1 = mn1;

        // ---- O += P V  (P fragments directly from softmax registers) ----
#pragma unroll
        for (int s = 0; s < 4; ++s) {
            uint32_t pah[4] = {ph2[2 * s][0], ph2[2 * s][1],
                               ph2[2 * s + 1][0], ph2[2 * s + 1][1]};
            uint32_t pal[4] = {pl2[2 * s][0], pl2[2 * s][1],
                               pl2[2 * s + 1][0], pl2[2 * s + 1][1]};
            uint32_t vhF[8][2], vlF[8][2];
#pragma unroll
            for (int pair = 0; pair < 4; ++pair) {
                int atom = pair * 2 + (mat >> 1);
                int kc = 16 * s + (mat & 1) * 8;
                int nrow = atom * 8 + mrw;
                uint32_t r0, r1, r2, r3;
                ldmx4(smem_u32(&sVh[nrow * ALD + kc]), r0, r1, r2, r3);
                vhF[pair * 2][0] = r0; vhF[pair * 2][1] = r1;
                vhF[pair * 2 + 1][0] = r2; vhF[pair * 2 + 1][1] = r3;
                ldmx4(smem_u32(&sVl[nrow * ALD + kc]), r0, r1, r2, r3);
                vlF[pair * 2][0] = r0; vlF[pair * 2][1] = r1;
                vlF[pair * 2 + 1][0] = r2; vlF[pair * 2 + 1][1] = r3;
            }
#pragma unroll
            for (int j = 0; j < 8; ++j) {
                mma_bf16(o[j], pah, vhF[j]);
                mma_bf16(o[j], pah, vlF[j]);
                mma_bf16(o[j], pal, vhF[j]);
            }
        }
    }

    // ---- epilogue: normalize and write ctx [B,T,D] ----
    float inv0 = 1.0f / l0r;
    float inv1 = 1.0f / l1r;
    int t0 = qt * 128 + warp * 16 + gid;
    int t1 = t0 + 8;
#pragma unroll
    for (int j = 0; j < 8; ++j) {
        int col = h * HDIM + j * 8 + tig * 2;
        float2 r0 = {o[j][0] * inv0, o[j][1] * inv0};
        float2 r1 = {o[j][2] * inv1, o[j][3] * inv1};
        *reinterpret_cast<float2*>(&ctx[((size_t)(b * SEQ + t0)) * DMODEL + col]) = r0;
        *reinterpret_cast<float2*>(&ctx[((size_t)(b * SEQ + t1)) * DMODEL + col]) = r1;
    }
}

// ---------------- LayerNorm: one block per row, 128 threads, D=512 --------
__global__ __launch_bounds__(128)
void ln_kernel(const float* __restrict__ in, const float* __restrict__ g,
               const float* __restrict__ beta, float* __restrict__ out) {
    __shared__ float red[8];
    const int row = blockIdx.x;
    const int tid = threadIdx.x;
    const int lane = tid & 31;
    const int wid = tid >> 5;

    float4 x4 = *reinterpret_cast<const float4*>(in + (size_t)row * DMODEL + tid * 4);
    float s = x4.x + x4.y + x4.z + x4.w;
#pragma unroll
    for (int off = 16; off; off >>= 1) s += __shfl_xor_sync(0xffffffffu, s, off);
    if (lane == 0) red[wid] = s;
    __syncthreads();
    float mean = (red[0] + red[1] + red[2] + red[3]) * (1.0f / DMODEL);

    float d0 = x4.x - mean, d1 = x4.y - mean, d2 = x4.z - mean, d3 = x4.w - mean;
    float sq = d0 * d0 + d1 * d1 + d2 * d2 + d3 * d3;
#pragma unroll
    for (int off = 16; off; off >>= 1) sq += __shfl_xor_sync(0xffffffffu, sq, off);
    if (lane == 0) red[4 + wid] = sq;
    __syncthreads();
    float var = (red[4] + red[5] + red[6] + red[7]) * (1.0f / DMODEL);
    float rstd = rsqrtf(var + 1e-5f);

    float4 g4 = *reinterpret_cast<const float4*>(g + tid * 4);
    float4 b4 = *reinterpret_cast<const float4*>(beta + tid * 4);
    float4 y;
    y.x = d0 * rstd * g4.x + b4.x;
    y.y = d1 * rstd * g4.y + b4.y;
    y.z = d2 * rstd * g4.z + b4.z;
    y.w = d3 * rstd * g4.w + b4.w;
    *reinterpret_cast<float4*>(out + (size_t)row * DMODEL + tid * 4) = y;
}

// ---------------- host-side orchestration ---------------------------------
extern "C" void kernel_launch(void* const* d_in, const int* in_sizes, int n_in,
                              void* d_out, int out_size) {
    const float* src = (const float*)d_in[0];
    const float* Wq = (const float*)d_in[1];
    const float* bq = (const float*)d_in[2];
    const float* Wk = (const float*)d_in[3];
    const float* bk = (const float*)d_in[4];
    const float* Wv = (const float*)d_in[5];
    const float* bv = (const float*)d_in[6];
    const float* Wo = (const float*)d_in[7];
    const float* bo = (const float*)d_in[8];
    const float* W1 = (const float*)d_in[9];
    const float* b1 = (const float*)d_in[10];
    const float* W2 = (const float*)d_in[11];
    const float* b2 = (const float*)d_in[12];
    const float* g1 = (const float*)d_in[13];
    const float* be1 = (const float*)d_in[14];
    const float* g2 = (const float*)d_in[15];
    const float* be2 = (const float*)d_in[16];
    float* outp = (float*)d_out;

    void *pq, *pk, *pv, *pctx, *ptmp, *px1, *ph;
    cudaGetSymbolAddress(&pq, g_q);
    cudaGetSymbolAddress(&pk, g_k);
    cudaGetSymbolAddress(&pv, g_v);
    cudaGetSymbolAddress(&pctx, g_ctx);
    cudaGetSymbolAddress(&ptmp, g_tmp);
    cudaGetSymbolAddress(&px1, g_x1);
    cudaGetSymbolAddress(&ph, g_h);
    float* Q = (float*)pq;
    float* K = (float*)pk;
    float* V = (float*)pv;
    float* CTX = (float*)pctx;
    float* TMP = (float*)ptmp;
    float* X1 = (float*)px1;
    float* HID = (float*)ph;

    cudaFuncSetAttribute(attn_mma, cudaFuncAttributeMaxDynamicSharedMemorySize,
                         ATTN_SMEM);

    dim3 blk(256);
    dim3 grid_d(DMODEL / 128, MROWS / 128);   // (4, 64)
    dim3 grid_ff(DFF / 128, MROWS / 128);     // (16, 64)

    // Q/K/V projections -> [BH, T, 64]
    gemm_mma<0><<<grid_d, blk>>>(src, Wq, bq, nullptr, Q, MROWS, DMODEL, DMODEL);
    gemm_mma<0><<<grid_d, blk>>>(src, Wk, bk, nullptr, K, MROWS, DMODEL, DMODEL);
    gemm_mma<0><<<grid_d, blk>>>(src, Wv, bv, nullptr, V, MROWS, DMODEL, DMODEL);

    // attention -> ctx [B,T,D]
    attn_mma<<<dim3(BATCH * NHEAD, SEQ / 128), blk, ATTN_SMEM>>>(Q, K, V, CTX);

    // O-proj + bias + residual(src) -> TMP ; LN1 -> X1
    gemm_mma<1><<<grid_d, blk>>>(CTX, Wo, bo, src, TMP, MROWS, DMODEL, DMODEL);
    ln_kernel<<<MROWS, 128>>>(TMP, g1, be1, X1);

    // FFN1 + GELU -> HID
    gemm_mma<2><<<grid_ff, blk>>>(X1, W1, b1, nullptr, HID, MROWS, DFF, DMODEL);

    // FFN2 + bias + residual(X1) -> TMP ; LN2 -> out
    gemm_mma<1><<<grid_d, blk>>>(HID, W2, b2, X1, TMP, MROWS, DMODEL, DFF);
    ln_kernel<<<MROWS, 128>>>(TMP, g2, be2, outp);
}

// round 11
// speedup vs baseline: 2.9447x; 1.4182x over previous
#include <cuda_runtime.h>
#include <cuda_bf16.h>
#include <math.h>
#include <stdint.h>

// Problem constants
#define BATCH 4
#define SEQ   2048
#define DMODEL 512
#define NHEAD 8
#define HDIM  64
#define DFF   2048
#define MROWS (BATCH * SEQ)   // 8192

#define ACT   (MROWS * DMODEL)        // 4,194,304
#define WSQ   (DMODEL * DMODEL)       // 262,144
#define WFF   (DFF * DMODEL)          // 1,048,576
#define WTOT  (4 * WSQ + 2 * WFF)     // 3,145,728

// weight offsets in combined split-weight buffers
#define OFF_WQ 0
#define OFF_WK (1 * WSQ)
#define OFF_WV (2 * WSQ)
#define OFF_WO (3 * WSQ)
#define OFF_W1 (4 * WSQ)
#define OFF_W2 (4 * WSQ + WFF)

// ---------------- scratch (static device arrays; no allocation allowed) ----
__device__ __nv_bfloat16 s_srch[ACT], s_srcl[ACT];
__device__ __nv_bfloat16 s_qh[ACT], s_ql[ACT];
__device__ __nv_bfloat16 s_kh[ACT], s_kl[ACT];
__device__ __nv_bfloat16 s_vh[ACT], s_vl[ACT];
__device__ __nv_bfloat16 s_ctxh[ACT], s_ctxl[ACT];
__device__ __nv_bfloat16 s_x1h[ACT], s_x1l[ACT];
__device__ __nv_bfloat16 s_hidh[MROWS * DFF], s_hidl[MROWS * DFF];
__device__ __nv_bfloat16 s_wh[WTOT], s_wl[WTOT];
__device__ float g_tmp[ACT];     // pre-LN fp32
__device__ float g_x1[ACT];      // post-LN1 fp32 (residual for FFN2)

// ---------------- common helpers -------------------------------------------
__device__ __forceinline__ uint32_t smem_u32(const void* p) {
    return (uint32_t)__cvta_generic_to_shared(p);
}

__device__ __forceinline__ void ldmx4(uint32_t addr, uint32_t& r0, uint32_t& r1,
                                      uint32_t& r2, uint32_t& r3) {
    asm volatile("ldmatrix.sync.aligned.m8n8.x4.shared.b16 {%0,%1,%2,%3}, [%4];"
                 : "=r"(r0), "=r"(r1), "=r"(r2), "=r"(r3) : "r"(addr));
}

__device__ __forceinline__ void mma_bf16(float* c, const uint32_t* a, const uint32_t* b) {
    asm volatile(
        "mma.sync.aligned.m16n8k16.row.col.f32.bf16.bf16.f32 "
        "{%0,%1,%2,%3}, {%4,%5,%6,%7}, {%8,%9}, {%0,%1,%2,%3};"
        : "+f"(c[0]), "+f"(c[1]), "+f"(c[2]), "+f"(c[3])
        : "r"(a[0]), "r"(a[1]), "r"(a[2]), "r"(a[3]), "r"(b[0]), "r"(b[1]));
}

__device__ __forceinline__ void split2(float x, float y, uint32_t& hi, uint32_t& lo) {
    __nv_bfloat16 xh = __float2bfloat16_rn(x);
    __nv_bfloat16 yh = __float2bfloat16_rn(y);
    __nv_bfloat16 xl = __float2bfloat16_rn(x - __bfloat162float(xh));
    __nv_bfloat16 yl = __float2bfloat16_rn(y - __bfloat162float(yh));
    __nv_bfloat162 h2(xh, yh), l2(xl, yl);
    hi = *reinterpret_cast<uint32_t*>(&h2);
    lo = *reinterpret_cast<uint32_t*>(&l2);
}

__device__ __forceinline__ void cpa16(uint32_t dst, const void* src) {
    asm volatile("cp.async.cg.shared.global [%0], [%1], 16;\n" ::"r"(dst), "l"(src));
}
__device__ __forceinline__ void cpa_commit() {
    asm volatile("cp.async.commit_group;\n" ::);
}
template <int N>
__device__ __forceinline__ void cpa_wait() {
    asm volatile("cp.async.wait_group %0;\n" ::"n"(N));
}

// ---------------- split pass: fp32 -> bf16 hi/lo ---------------------------
__global__ __launch_bounds__(256)
void split_kernel(const float* __restrict__ in, __nv_bfloat16* __restrict__ hi,
                  __nv_bfloat16* __restrict__ lo, int n4) {
    int i = blockIdx.x * blockDim.x + threadIdx.x;
    if (i < n4) {
        float4 v = reinterpret_cast<const float4*>(in)[i];
        uint32_t h0, l0, h1, l1;
        split2(v.x, v.y, h0, l0);
        split2(v.z, v.w, h1, l1);
        reinterpret_cast<uint32_t*>(hi)[i * 2]     = h0;
        reinterpret_cast<uint32_t*>(hi)[i * 2 + 1] = h1;
        reinterpret_cast<uint32_t*>(lo)[i * 2]     = l0;
        reinterpret_cast<uint32_t*>(lo)[i * 2 + 1] = l1;
    }
}

// ================= pre-split bf16 tensor-core GEMM =========================
// C = A (MxK) * B^T, A/B given as bf16 hi/lo arrays. 3 MMAs (hh+hl+lh).
// Block 128x128, BK=32, 256 threads (2m x 4n warps), cp.async double-buffered.
// EPI 0: heads scatter + bias -> split bf16 out
// EPI 1: bias + residual -> fp32 out
// EPI 2: bias + GELU -> split bf16 out
#define LDK 40
#define GEMM_SZ (128 * LDK)                 // elements per smem array
#define GEMM_SMEM (2 * 4 * GEMM_SZ * 2)     // 81920 bytes

template <int EPI>
__global__ __launch_bounds__(256)
void gemm_mma2(const __nv_bfloat16* __restrict__ Ah, const __nv_bfloat16* __restrict__ Al,
               const __nv_bfloat16* __restrict__ Bh, const __nv_bfloat16* __restrict__ Bl,
               const float* __restrict__ bias, const float* __restrict__ res,
               float* __restrict__ outf, __nv_bfloat16* __restrict__ outh,
               __nv_bfloat16* __restrict__ outl, int M, int N, int K) {
    extern __shared__ __nv_bfloat16 smg[];

    const int tid = threadIdx.x;
    const int warp = tid >> 5;
    const int lane = tid & 31;
    const int wm = (warp & 1) * 64;
    const int wn = (warp >> 1) * 32;
    const int bm = blockIdx.y * 128;
    const int bn = blockIdx.x * 128;
    const int mat = lane >> 3;
    const int mrw = lane & 7;

    float acc[4][4][4];
#pragma unroll
    for (int i = 0; i < 4; ++i)
#pragma unroll
        for (int j = 0; j < 4; ++j)
#pragma unroll
            for (int c = 0; c < 4; ++c) acc[i][j][c] = 0.0f;

    auto load_stage = [&](int k0, int st) {
        __nv_bfloat16* base = smg + st * 4 * GEMM_SZ;
#pragma unroll
        for (int it = 0; it < 2; ++it) {
            int idx = it * 256 + tid;           // 0..511
            int row = idx >> 2;
            int ch = (idx & 3) * 8;             // col (8 bf16 = 16B)
            int so = row * LDK + ch;
            size_t ga = (size_t)(bm + row) * K + k0 + ch;
            size_t gb = (size_t)(bn + row) * K + k0 + ch;
            cpa16(smem_u32(base + so), Ah + ga);
            cpa16(smem_u32(base + GEMM_SZ + so), Al + ga);
            cpa16(smem_u32(base + 2 * GEMM_SZ + so), Bh + gb);
            cpa16(smem_u32(base + 3 * GEMM_SZ + so), Bl + gb);
        }
    };

    const int nk = K / 32;
    load_stage(0, 0);
    cpa_commit();

    for (int i = 0; i < nk; ++i) {
        if (i + 1 < nk) {
            load_stage((i + 1) * 32, (i + 1) & 1);
            cpa_commit();
            cpa_wait<1>();
        } else {
            cpa_wait<0>();
        }
        __syncthreads();

        const __nv_bfloat16* base = smg + (i & 1) * 4 * GEMM_SZ;
        const __nv_bfloat16* sAh = base;
        const __nv_bfloat16* sAl = base + GEMM_SZ;
        const __nv_bfloat16* sBh = base + 2 * GEMM_SZ;
        const __nv_bfloat16* sBl = base + 3 * GEMM_SZ;

#pragma unroll
        for (int ks = 0; ks < 32; ks += 16) {
            uint32_t bhF[4][2], blF[4][2];
#pragma unroll
            for (int pair = 0; pair < 2; ++pair) {
                int atom = pair * 2 + (mat >> 1);
                int kc = ks + (mat & 1) * 8;
                int nrow = wn + atom * 8 + mrw;
                uint32_t r0, r1, r2, r3;
                ldmx4(smem_u32(&sBh[nrow * LDK + kc]), r0, r1, r2, r3);
                bhF[pair * 2][0] = r0; bhF[pair * 2][1] = r1;
                bhF[pair * 2 + 1][0] = r2; bhF[pair * 2 + 1][1] = r3;
                ldmx4(smem_u32(&sBl[nrow * LDK + kc]), r0, r1, r2, r3);
                blF[pair * 2][0] = r0; blF[pair * 2][1] = r1;
                blF[pair * 2 + 1][0] = r2; blF[pair * 2 + 1][1] = r3;
            }
#pragma unroll
            for (int am = 0; am < 4; ++am) {
                int arow = wm + am * 16 + (mat & 1) * 8 + mrw;
                int akc = ks + (mat >> 1) * 8;
                uint32_t ahF[4], alF[4];
                ldmx4(smem_u32(&sAh[arow * LDK + akc]), ahF[0], ahF[1], ahF[2], ahF[3]);
                ldmx4(smem_u32(&sAl[arow * LDK + akc]), alF[0], alF[1], alF[2], alF[3]);
#pragma unroll
                for (int an = 0; an < 4; ++an) {
                    mma_bf16(acc[am][an], ahF, bhF[an]);
                    mma_bf16(acc[am][an], ahF, blF[an]);
                    mma_bf16(acc[am][an], alF, bhF[an]);
                }
            }
        }
        __syncthreads();
    }

    // ---- epilogue ----
    const int gid = lane >> 2;
    const int tig = lane & 3;
#pragma unroll
    for (int am = 0; am < 4; ++am) {
#pragma unroll
        for (int an = 0; an < 4; ++an) {
            int m0 = bm + wm + am * 16 + gid;
            int m1 = m0 + 8;
            int n0 = bn + wn + an * 8 + tig * 2;
            float bs0 = bias[n0], bs1 = bias[n0 + 1];
            float v00 = acc[am][an][0] + bs0;
            float v01 = acc[am][an][1] + bs1;
            float v10 = acc[am][an][2] + bs0;
            float v11 = acc[am][an][3] + bs1;
            if (EPI == 0) {
                // heads scatter: n0 even, same head for n0,n0+1
                int hh = n0 >> 6, dh = n0 & 63;
                size_t i0 = (((size_t)((m0 >> 11) * NHEAD + hh) * SEQ) + (m0 & 2047)) * HDIM + dh;
                size_t i1 = (((size_t)((m1 >> 11) * NHEAD + hh) * SEQ) + (m1 & 2047)) * HDIM + dh;
                uint32_t hw, lw;
                split2(v00, v01, hw, lw);
                *reinterpret_cast<uint32_t*>(&outh[i0]) = hw;
                *reinterpret_cast<uint32_t*>(&outl[i0]) = lw;
                split2(v10, v11, hw, lw);
                *reinterpret_cast<uint32_t*>(&outh[i1]) = hw;
                *reinterpret_cast<uint32_t*>(&outl[i1]) = lw;
            } else if (EPI == 1) {
                size_t o0 = (size_t)m0 * N + n0;
                size_t o1 = (size_t)m1 * N + n0;
                float2 r0 = *reinterpret_cast<const float2*>(&res[o0]);
                float2 r1 = *reinterpret_cast<const float2*>(&res[o1]);
                float2 w0 = {v00 + r0.x, v01 + r0.y};
                float2 w1 = {v10 + r1.x, v11 + r1.y};
                *reinterpret_cast<float2*>(&outf[o0]) = w0;
                *reinterpret_cast<float2*>(&outf[o1]) = w1;
            } else {
                size_t o0 = (size_t)m0 * N + n0;
                size_t o1 = (size_t)m1 * N + n0;
                float g00 = 0.5f * v00 * (1.0f + erff(v00 * 0.70710678118654752f));
                float g01 = 0.5f * v01 * (1.0f + erff(v01 * 0.70710678118654752f));
                float g10 = 0.5f * v10 * (1.0f + erff(v10 * 0.70710678118654752f));
                float g11 = 0.5f * v11 * (1.0f + erff(v11 * 0.70710678118654752f));
                uint32_t hw, lw;
                split2(g00, g01, hw, lw);
                *reinterpret_cast<uint32_t*>(&outh[o0]) = hw;
                *reinterpret_cast<uint32_t*>(&outl[o0]) = lw;
                split2(g10, g11, hw, lw);
                *reinterpret_cast<uint32_t*>(&outh[o1]) = hw;
                *reinterpret_cast<uint32_t*>(&outl[o1]) = lw;
            }
        }
    }
}

// ================= tensor-core flash attention (pre-split bf16) ============
// grid (BH=32, SEQ/128=16), 256 threads (8 warps), 16 q rows/warp, 64-key tiles.
#define ALD 72
#define ATTN_SMEM ((2 * 128 + 4 * 64) * ALD * 2)   // 73728 bytes

__global__ __launch_bounds__(256, 2)
void attn_mma2(const __nv_bfloat16* __restrict__ qh, const __nv_bfloat16* __restrict__ ql,
               const __nv_bfloat16* __restrict__ kh, const __nv_bfloat16* __restrict__ kl,
               const __nv_bfloat16* __restrict__ vh, const __nv_bfloat16* __restrict__ vl,
               __nv_bfloat16* __restrict__ ctxh, __nv_bfloat16* __restrict__ ctxl) {
    extern __shared__ __nv_bfloat16 sm[];
    __nv_bfloat16* sQh = sm;                     // [128][ALD]
    __nv_bfloat16* sQl = sQh + 128 * ALD;
    __nv_bfloat16* sKh = sQl + 128 * ALD;        // [64][ALD]
    __nv_bfloat16* sKl = sKh + 64 * ALD;
    __nv_bfloat16* sVh = sKl + 64 * ALD;         // [64][ALD]  V^T: [d][kk]
    __nv_bfloat16* sVl = sVh + 64 * ALD;

    const int bh = blockIdx.x;
    const int qt = blockIdx.y;
    const int b = bh >> 3;
    const int h = bh & 7;
    const int tid = threadIdx.x;
    const int warp = tid >> 5;
    const int lane = tid & 31;
    const int mat = lane >> 3;
    const int mrw = lane & 7;
    const int gid = lane >> 2;
    const int tig = lane & 3;

    const size_t qoff = ((size_t)bh * SEQ + qt * 128) * HDIM;
    const size_t koff = (size_t)bh * SEQ * HDIM;

    // ---- load Q tile 128x64 (pure bf16 copies) ----
#pragma unroll
    for (int it = 0; it < 4; ++it) {
        int idx = it * 256 + tid;         // 1024 chunks
        int row = idx >> 3;
        int ch = (idx & 7) * 8;
        int so = row * ALD + ch;
        *reinterpret_cast<uint4*>(&sQh[so]) =
            *reinterpret_cast<const uint4*>(&qh[qoff + row * HDIM + ch]);
        *reinterpret_cast<uint4*>(&sQl[so]) =
            *reinterpret_cast<const uint4*>(&ql[qoff + row * HDIM + ch]);
    }

    float o[8][4];
#pragma unroll
    for (int j = 0; j < 8; ++j)
#pragma unroll
        for (int c = 0; c < 4; ++c) o[j][c] = 0.0f;
    float m0 = -1e30f, m1 = -1e30f, l0r = 0.0f, l1r = 0.0f;

    for (int kt = 0; kt < SEQ / 64; ++kt) {
        __syncthreads();
        const size_t toff = koff + (size_t)kt * 64 * HDIM;
#pragma unroll
        for (int it = 0; it < 2; ++it) {
            int idx = it * 256 + tid;      // 512 chunks
            int row = idx >> 3;            // kk
            int ch = (idx & 7) * 8;        // d
            int so = row * ALD + ch;
            *reinterpret_cast<uint4*>(&sKh[so]) =
                *reinterpret_cast<const uint4*>(&kh[toff + row * HDIM + ch]);
            *reinterpret_cast<uint4*>(&sKl[so]) =
                *reinterpret_cast<const uint4*>(&kl[toff + row * HDIM + ch]);
            // V transposed scatter
            uint4 hv = *reinterpret_cast<const uint4*>(&vh[toff + row * HDIM + ch]);
            uint4 lv = *reinterpret_cast<const uint4*>(&vl[toff + row * HDIM + ch]);
            __nv_bfloat16 ht[8], lt[8];
            *reinterpret_cast<uint4*>(ht) = hv;
            *reinterpret_cast<uint4*>(lt) = lv;
#pragma unroll
            for (int e = 0; e < 8; ++e) {
                sVh[(ch + e) * ALD + row] = ht[e];
                sVl[(ch + e) * ALD + row] = lt[e];
            }
        }
        __syncthreads();

        // ---- S = Q K^T : warp computes 16x64 ----
        float sa[8][4];
#pragma unroll
        for (int j = 0; j < 8; ++j)
#pragma unroll
            for (int c = 0; c < 4; ++c) sa[j][c] = 0.0f;

#pragma unroll
        for (int s = 0; s < 4; ++s) {
            int akc = 16 * s + (mat >> 1) * 8;
            int arow = 16 * warp + (mat & 1) * 8 + mrw;
            uint32_t qhF[4], qlF[4];
            ldmx4(smem_u32(&sQh[arow * ALD + akc]), qhF[0], qhF[1], qhF[2], qhF[3]);
            ldmx4(smem_u32(&sQl[arow * ALD + akc]), qlF[0], qlF[1], qlF[2], qlF[3]);
            uint32_t khF[8][2], klF[8][2];
#pragma unroll
            for (int pair = 0; pair < 4; ++pair) {
                int atom = pair * 2 + (mat >> 1);
                int kc = 16 * s + (mat & 1) * 8;
                int nrow = atom * 8 + mrw;
                uint32_t r0, r1, r2, r3;
                ldmx4(smem_u32(&sKh[nrow * ALD + kc]), r0, r1, r2, r3);
                khF[pair * 2][0] = r0; khF[pair * 2][1] = r1;
                khF[pair * 2 + 1][0] = r2; khF[pair * 2 + 1][1] = r3;
                ldmx4(smem_u32(&sKl[nrow * ALD + kc]), r0, r1, r2, r3);
                klF[pair * 2][0] = r0; klF[pair * 2][1] = r1;
                klF[pair * 2 + 1][0] = r2; klF[pair * 2 + 1][1] = r3;
            }
#pragma unroll
            for (int j = 0; j < 8; ++j) {
                mma_bf16(sa[j], qhF, khF[j]);
                mma_bf16(sa[j], qhF, klF[j]);
                mma_bf16(sa[j], qlF, khF[j]);
            }
        }

        // ---- online softmax ----
        float mx0 = -1e30f, mx1 = -1e30f;
#pragma unroll
        for (int j = 0; j < 8; ++j) {
            sa[j][0] *= 0.125f; sa[j][1] *= 0.125f;
            sa[j][2] *= 0.125f; sa[j][3] *= 0.125f;
            mx0 = fmaxf(mx0, fmaxf(sa[j][0], sa[j][1]));
            mx1 = fmaxf(mx1, fmaxf(sa[j][2], sa[j][3]));
        }
        mx0 = fmaxf(mx0, __shfl_xor_sync(0xffffffffu, mx0, 1));
        mx0 = fmaxf(mx0, __shfl_xor_sync(0xffffffffu, mx0, 2));
        mx1 = fmaxf(mx1, __shfl_xor_sync(0xffffffffu, mx1, 1));
        mx1 = fmaxf(mx1, __shfl_xor_sync(0xffffffffu, mx1, 2));
        float mn0 = fmaxf(m0, mx0), mn1 = fmaxf(m1, mx1);
        float f0 = __expf(m0 - mn0), f1 = __expf(m1 - mn1);

        float rs0 = 0.0f, rs1 = 0.0f;
        uint32_t ph2[8][2], pl2[8][2];
#pragma unroll
        for (int j = 0; j < 8; ++j) {
            float p0 = __expf(sa[j][0] - mn0);
            float p1 = __expf(sa[j][1] - mn0);
            float p2 = __expf(sa[j][2] - mn1);
            float p3 = __expf(sa[j][3] - mn1);
            rs0 += p0 + p1;
            rs1 += p2 + p3;
            split2(p0, p1, ph2[j][0], pl2[j][0]);
            split2(p2, p3, ph2[j][1], pl2[j][1]);
            o[j][0] *= f0; o[j][1] *= f0;
            o[j][2] *= f1; o[j][3] *= f1;
        }
        rs0 += __shfl_xor_sync(0xffffffffu, rs0, 1);
        rs0 += __shfl_xor_sync(0xffffffffu, rs0, 2);
        rs1 += __shfl_xor_sync(0xffffffffu, rs1, 1);
        rs1 += __shfl_xor_sync(0xffffffffu, rs1, 2);
        l0r = l0r * f0 + rs0;
        l1r = l1r * f1 + rs1;
        m0 = mn0; m1 = mn1;

        // ---- O += P V ----
#pragma unroll
        for (int s = 0; s < 4; ++s) {
            uint32_t pah[4] = {ph2[2 * s][0], ph2[2 * s][1],
                               ph2[2 * s + 1][0], ph2[2 * s + 1][1]};
            uint32_t pal[4] = {pl2[2 * s][0], pl2[2 * s][1],
                               pl2[2 * s + 1][0], pl2[2 * s + 1][1]};
            uint32_t vhF[8][2], vlF[8][2];
#pragma unroll
            for (int pair = 0; pair < 4; ++pair) {
                int atom = pair * 2 + (mat >> 1);
                int kc = 16 * s + (mat & 1) * 8;
                int nrow = atom * 8 + mrw;
                uint32_t r0, r1, r2, r3;
                ldmx4(smem_u32(&sVh[nrow * ALD + kc]), r0, r1, r2, r3);
                vhF[pair * 2][0] = r0; vhF[pair * 2][1] = r1;
                vhF[pair * 2 + 1][0] = r2; vhF[pair * 2 + 1][1] = r3;
                ldmx4(smem_u32(&sVl[nrow * ALD + kc]), r0, r1, r2, r3);
                vlF[pair * 2][0] = r0; vlF[pair * 2][1] = r1;
                vlF[pair * 2 + 1][0] = r2; vlF[pair * 2 + 1][1] = r3;
            }
#pragma unroll
            for (int j = 0; j < 8; ++j) {
                mma_bf16(o[j], pah, vhF[j]);
                mma_bf16(o[j], pah, vlF[j]);
                mma_bf16(o[j], pal, vhF[j]);
            }
        }
    }

    // ---- epilogue: normalize, split, write ctx hi/lo [B,T,D] ----
    float inv0 = 1.0f / l0r;
    float inv1 = 1.0f / l1r;
    int t0 = qt * 128 + warp * 16 + gid;
    int t1 = t0 + 8;
#pragma unroll
    for (int j = 0; j < 8; ++j) {
        int col = h * HDIM + j * 8 + tig * 2;
        size_t i0 = ((size_t)(b * SEQ + t0)) * DMODEL + col;
        size_t i1 = ((size_t)(b * SEQ + t1)) * DMODEL + col;
        uint32_t hw, lw;
        split2(o[j][0] * inv0, o[j][1] * inv0, hw, lw);
        *reinterpret_cast<uint32_t*>(&ctxh[i0]) = hw;
        *reinterpret_cast<uint32_t*>(&ctxl[i0]) = lw;
        split2(o[j][2] * inv1, o[j][3] * inv1, hw, lw);
        *reinterpret_cast<uint32_t*>(&ctxh[i1]) = hw;
        *reinterpret_cast<uint32_t*>(&ctxl[i1]) = lw;
    }
}

// ---------------- LayerNorm (optionally emits split bf16 too) --------------
template <int SPLIT>
__global__ __launch_bounds__(128)
void ln_kernel(const float* __restrict__ in, const float* __restrict__ g,
               const float* __restrict__ beta, float* __restrict__ out,
               __nv_bfloat16* __restrict__ outh, __nv_bfloat16* __restrict__ outl) {
    __shared__ float red[8];
    const int row = blockIdx.x;
    const int tid = threadIdx.x;
    const int lane = tid & 31;
    const int wid = tid >> 5;

    float4 x4 = *reinterpret_cast<const float4*>(in + (size_t)row * DMODEL + tid * 4);
    float s = x4.x + x4.y + x4.z + x4.w;
#pragma unroll
    for (int off = 16; off; off >>= 1) s += __shfl_xor_sync(0xffffffffu, s, off);
    if (lane == 0) red[wid] = s;
    __syncthreads();
    float mean = (red[0] + red[1] + red[2] + red[3]) * (1.0f / DMODEL);

    float d0 = x4.x - mean, d1 = x4.y - mean, d2 = x4.z - mean, d3 = x4.w - mean;
    float sq = d0 * d0 + d1 * d1 + d2 * d2 + d3 * d3;
#pragma unroll
    for (int off = 16; off; off >>= 1) sq += __shfl_xor_sync(0xffffffffu, sq, off);
    if (lane == 0) red[4 + wid] = sq;
    __syncthreads();
    float var = (red[4] + red[5] + red[6] + red[7]) * (1.0f / DMODEL);
    float rstd = rsqrtf(var + 1e-5f);

    float4 g4 = *reinterpret_cast<const float4*>(g + tid * 4);
    float4 b4 = *reinterpret_cast<const float4*>(beta + tid * 4);
    float4 y;
    y.x = d0 * rstd * g4.x + b4.x;
    y.y = d1 * rstd * g4.y + b4.y;
    y.z = d2 * rstd * g4.z + b4.z;
    y.w = d3 * rstd * g4.w + b4.w;
    *reinterpret_cast<float4*>(out + (size_t)row * DMODEL + tid * 4) = y;
    if (SPLIT) {
        size_t o0 = (size_t)row * DMODEL + tid * 4;
        uint32_t h0, l0, h1, l1;
        split2(y.x, y.y, h0, l0);
        split2(y.z, y.w, h1, l1);
        *reinterpret_cast<uint32_t*>(&outh[o0])     = h0;
        *reinterpret_cast<uint32_t*>(&outh[o0 + 2]) = h1;
        *reinterpret_cast<uint32_t*>(&outl[o0])     = l0;
        *reinterpret_cast<uint32_t*>(&outl[o0 + 2]) = l1;
    }
}

// ---------------- host-side orchestration ---------------------------------
extern "C" void kernel_launch(void* const* d_in, const int* in_sizes, int n_in,
                              void* d_out, int out_size) {
    const float* src = (const float*)d_in[0];
    const float* Wq = (const float*)d_in[1];
    const float* bq = (const float*)d_in[2];
    const float* Wk = (const float*)d_in[3];
    const float* bk = (const float*)d_in[4];
    const float* Wv = (const float*)d_in[5];
    const float* bv = (const float*)d_in[6];
    const float* Wo = (const float*)d_in[7];
    const float* bo = (const float*)d_in[8];
    const float* W1 = (const float*)d_in[9];
    const float* b1 = (const float*)d_in[10];
    const float* W2 = (const float*)d_in[11];
    const float* b2 = (const float*)d_in[12];
    const float* g1 = (const float*)d_in[13];
    const float* be1 = (const float*)d_in[14];
    const float* g2 = (const float*)d_in[15];
    const float* be2 = (const float*)d_in[16];
    float* outp = (float*)d_out;

    // resolve scratch symbols
    void* p;
#define SYM(name) cudaGetSymbolAddress(&p, name)
    __nv_bfloat16 *srch, *srcl, *qh, *ql, *kh, *kl, *vh, *vl;
    __nv_bfloat16 *ctxh, *ctxl, *x1h, *x1l, *hidh, *hidl, *wh, *wl;
    float *TMP, *X1;
    SYM(s_srch); srch = (__nv_bfloat16*)p;
    SYM(s_srcl); srcl = (__nv_bfloat16*)p;
    SYM(s_qh); qh = (__nv_bfloat16*)p;
    SYM(s_ql); ql = (__nv_bfloat16*)p;
    SYM(s_kh); kh = (__nv_bfloat16*)p;
    SYM(s_kl); kl = (__nv_bfloat16*)p;
    SYM(s_vh); vh = (__nv_bfloat16*)p;
    SYM(s_vl); vl = (__nv_bfloat16*)p;
    SYM(s_ctxh); ctxh = (__nv_bfloat16*)p;
    SYM(s_ctxl); ctxl = (__nv_bfloat16*)p;
    SYM(s_x1h); x1h = (__nv_bfloat16*)p;
    SYM(s_x1l); x1l = (__nv_bfloat16*)p;
    SYM(s_hidh); hidh = (__nv_bfloat16*)p;
    SYM(s_hidl); hidl = (__nv_bfloat16*)p;
    SYM(s_wh); wh = (__nv_bfloat16*)p;
    SYM(s_wl); wl = (__nv_bfloat16*)p;
    SYM(g_tmp); TMP = (float*)p;
    SYM(g_x1); X1 = (float*)p;
#undef SYM

    cudaFuncSetAttribute(attn_mma2, cudaFuncAttributeMaxDynamicSharedMemorySize,
                         ATTN_SMEM);
    cudaFuncSetAttribute(gemm_mma2<0>, cudaFuncAttributeMaxDynamicSharedMemorySize,
                         GEMM_SMEM);
    cudaFuncSetAttribute(gemm_mma2<1>, cudaFuncAttributeMaxDynamicSharedMemorySize,
                         GEMM_SMEM);
    cudaFuncSetAttribute(gemm_mma2<2>, cudaFuncAttributeMaxDynamicSharedMemorySize,
                         GEMM_SMEM);

    dim3 blk(256);
    dim3 grid_d(DMODEL / 128, MROWS / 128);   // (4, 64)
    dim3 grid_ff(DFF / 128, MROWS / 128);     // (16, 64)

    // ---- split src + weights ----
    split_kernel<<<ACT / 4 / 256, 256>>>(src, srch, srcl, ACT / 4);
    split_kernel<<<WSQ / 4 / 256, 256>>>(Wq, wh + OFF_WQ, wl + OFF_WQ, WSQ / 4);
    split_kernel<<<WSQ / 4 / 256, 256>>>(Wk, wh + OFF_WK, wl + OFF_WK, WSQ / 4);
    split_kernel<<<WSQ / 4 / 256, 256>>>(Wv, wh + OFF_WV, wl + OFF_WV, WSQ / 4);
    split_kernel<<<WSQ / 4 / 256, 256>>>(Wo, wh + OFF_WO, wl + OFF_WO, WSQ / 4);
    split_kernel<<<WFF / 4 / 256, 256>>>(W1, wh + OFF_W1, wl + OFF_W1, WFF / 4);
    split_kernel<<<WFF / 4 / 256, 256>>>(W2, wh + OFF_W2, wl + OFF_W2, WFF / 4);

    // ---- Q/K/V projections -> split [BH,T,64] ----
    gemm_mma2<0><<<grid_d, blk, GEMM_SMEM>>>(srch, srcl, wh + OFF_WQ, wl + OFF_WQ,
                                             bq, nullptr, nullptr, qh, ql,
                                             MROWS, DMODEL, DMODEL);
    gemm_mma2<0><<<grid_d, blk, GEMM_SMEM>>>(srch, srcl, wh + OFF_WK, wl + OFF_WK,
                                             bk, nullptr, nullptr, kh, kl,
                                             MROWS, DMODEL, DMODEL);
    gemm_mma2<0><<<grid_d, blk, GEMM_SMEM>>>(srch, srcl, wh + OFF_WV, wl + OFF_WV,
                                             bv, nullptr, nullptr, vh, vl,
                                             MROWS, DMODEL, DMODEL);

    // ---- attention -> split ctx [B,T,D] ----
    attn_mma2<<<dim3(BATCH * NHEAD, SEQ / 128), blk, ATTN_SMEM>>>(
        qh, ql, kh, kl, vh, vl, ctxh, ctxl);

    // ---- O-proj + bias + residual(src) -> TMP ; LN1 -> X1 fp32 + split ----
    gemm_mma2<1><<<grid_d, blk, GEMM_SMEM>>>(ctxh, ctxl, wh + OFF_WO, wl + OFF_WO,
                                             bo, src, TMP, nullptr, nullptr,
                                             MROWS, DMODEL, DMODEL);
    ln_kernel<1><<<MROWS, 128>>>(TMP, g1, be1, X1, x1h, x1l);

    // ---- FFN1 + GELU -> split HID ----
    gemm_mma2<2><<<grid_ff, blk, GEMM_SMEM>>>(x1h, x1l, wh + OFF_W1, wl + OFF_W1,
                                              b1, nullptr, nullptr, hidh, hidl,
                                              MROWS, DFF, DMODEL);

    // ---- FFN2 + bias + residual(X1) -> TMP ; LN2 -> out ----
    gemm_mma2<1><<<grid_d, blk, GEMM_SMEM>>>(hidh, hidl, wh + OFF_W2, wl + OFF_W2,
                                             b2, X1, TMP, nullptr, nullptr,
                                             MROWS, DMODEL, DFF);
    ln_kernel<0><<<MROWS, 128>>>(TMP, g2, be2, outp, nullptr, nullptr);
}

// round 12
// speedup vs baseline: 3.3470x; 1.1366x over previous
#include <cuda_runtime.h>
#include <cuda_bf16.h>
#include <math.h>
#include <stdint.h>

// Problem constants
#define BATCH 4
#define SEQ   2048
#define DMODEL 512
#define NHEAD 8
#define HDIM  64
#define DFF   2048
#define MROWS (BATCH * SEQ)   // 8192

#define ACT   (MROWS * DMODEL)        // 4,194,304
#define WSQ   (DMODEL * DMODEL)       // 262,144
#define WFF   (DFF * DMODEL)          // 1,048,576
#define WTOT  (4 * WSQ + 2 * WFF)     // 3,145,728

// weight offsets in combined split-weight buffers
#define OFF_WQ 0
#define OFF_WK (1 * WSQ)
#define OFF_WV (2 * WSQ)
#define OFF_WO (3 * WSQ)
#define OFF_W1 (4 * WSQ)
#define OFF_W2 (4 * WSQ + WFF)

// ---------------- scratch (static device arrays; no allocation allowed) ----
__device__ __nv_bfloat16 s_srch[ACT], s_srcl[ACT];
__device__ __nv_bfloat16 s_qh[ACT], s_ql[ACT];
__device__ __nv_bfloat16 s_kh[ACT], s_kl[ACT];
__device__ __nv_bfloat16 s_vh[ACT], s_vl[ACT];
__device__ __nv_bfloat16 s_ctxh[ACT], s_ctxl[ACT];
__device__ __nv_bfloat16 s_x1h[ACT], s_x1l[ACT];
__device__ __nv_bfloat16 s_hidh[MROWS * DFF], s_hidl[MROWS * DFF];
__device__ __nv_bfloat16 s_wh[WTOT], s_wl[WTOT];
__device__ float g_tmp[ACT];     // pre-LN fp32
__device__ float g_x1[ACT];      // post-LN1 fp32 (residual for FFN2)

// ---------------- common helpers -------------------------------------------
__device__ __forceinline__ uint32_t smem_u32(const void* p) {
    return (uint32_t)__cvta_generic_to_shared(p);
}

__device__ __forceinline__ void ldmx4(uint32_t addr, uint32_t& r0, uint32_t& r1,
                                      uint32_t& r2, uint32_t& r3) {
    asm volatile("ldmatrix.sync.aligned.m8n8.x4.shared.b16 {%0,%1,%2,%3}, [%4];"
                 : "=r"(r0), "=r"(r1), "=r"(r2), "=r"(r3) : "r"(addr));
}

__device__ __forceinline__ void ldmx4t(uint32_t addr, uint32_t& r0, uint32_t& r1,
                                       uint32_t& r2, uint32_t& r3) {
    asm volatile("ldmatrix.sync.aligned.m8n8.x4.trans.shared.b16 {%0,%1,%2,%3}, [%4];"
                 : "=r"(r0), "=r"(r1), "=r"(r2), "=r"(r3) : "r"(addr));
}

__device__ __forceinline__ void mma_bf16(float* c, const uint32_t* a, const uint32_t* b) {
    asm volatile(
        "mma.sync.aligned.m16n8k16.row.col.f32.bf16.bf16.f32 "
        "{%0,%1,%2,%3}, {%4,%5,%6,%7}, {%8,%9}, {%0,%1,%2,%3};"
        : "+f"(c[0]), "+f"(c[1]), "+f"(c[2]), "+f"(c[3])
        : "r"(a[0]), "r"(a[1]), "r"(a[2]), "r"(a[3]), "r"(b[0]), "r"(b[1]));
}

__device__ __forceinline__ void split2(float x, float y, uint32_t& hi, uint32_t& lo) {
    __nv_bfloat16 xh = __float2bfloat16_rn(x);
    __nv_bfloat16 yh = __float2bfloat16_rn(y);
    __nv_bfloat16 xl = __float2bfloat16_rn(x - __bfloat162float(xh));
    __nv_bfloat16 yl = __float2bfloat16_rn(y - __bfloat162float(yh));
    __nv_bfloat162 h2(xh, yh), l2(xl, yl);
    hi = *reinterpret_cast<uint32_t*>(&h2);
    lo = *reinterpret_cast<uint32_t*>(&l2);
}

__device__ __forceinline__ void cpa16(uint32_t dst, const void* src) {
    asm volatile("cp.async.cg.shared.global [%0], [%1], 16;\n" ::"r"(dst), "l"(src));
}
__device__ __forceinline__ void cpa_commit() {
    asm volatile("cp.async.commit_group;\n" ::);
}
template <int N>
__device__ __forceinline__ void cpa_wait() {
    asm volatile("cp.async.wait_group %0;\n" ::"n"(N));
}

// ---------------- split pass: fp32 -> bf16 hi/lo ---------------------------
__global__ __launch_bounds__(256)
void split_kernel(const float* __restrict__ in, __nv_bfloat16* __restrict__ hi,
                  __nv_bfloat16* __restrict__ lo, int n4) {
    int i = blockIdx.x * blockDim.x + threadIdx.x;
    if (i < n4) {
        float4 v = reinterpret_cast<const float4*>(in)[i];
        uint32_t h0, l0, h1, l1;
        split2(v.x, v.y, h0, l0);
        split2(v.z, v.w, h1, l1);
        reinterpret_cast<uint32_t*>(hi)[i * 2]     = h0;
        reinterpret_cast<uint32_t*>(hi)[i * 2 + 1] = h1;
        reinterpret_cast<uint32_t*>(lo)[i * 2]     = l0;
        reinterpret_cast<uint32_t*>(lo)[i * 2 + 1] = l1;
    }
}

// ================= pre-split bf16 tensor-core GEMM =========================
// C = A (MxK) * B^T, A/B given as bf16 hi/lo arrays. 3 MMAs (hh+hl+lh).
// Block 128x128, BK=32, 256 threads (2m x 4n warps), cp.async double-buffered.
#define LDK 40
#define GEMM_SZ (128 * LDK)                 // elements per smem array
#define GEMM_SMEM (2 * 4 * GEMM_SZ * 2)     // 81920 bytes

template <int EPI>
__global__ __launch_bounds__(256)
void gemm_mma2(const __nv_bfloat16* __restrict__ Ah, const __nv_bfloat16* __restrict__ Al,
               const __nv_bfloat16* __restrict__ Bh, const __nv_bfloat16* __restrict__ Bl,
               const float* __restrict__ bias, const float* __restrict__ res,
               float* __restrict__ outf, __nv_bfloat16* __restrict__ outh,
               __nv_bfloat16* __restrict__ outl, int M, int N, int K) {
    extern __shared__ __nv_bfloat16 smg[];

    const int tid = threadIdx.x;
    const int warp = tid >> 5;
    const int lane = tid & 31;
    const int wm = (warp & 1) * 64;
    const int wn = (warp >> 1) * 32;
    const int bm = blockIdx.y * 128;
    const int bn = blockIdx.x * 128;
    const int mat = lane >> 3;
    const int mrw = lane & 7;

    float acc[4][4][4];
#pragma unroll
    for (int i = 0; i < 4; ++i)
#pragma unroll
        for (int j = 0; j < 4; ++j)
#pragma unroll
            for (int c = 0; c < 4; ++c) acc[i][j][c] = 0.0f;

    auto load_stage = [&](int k0, int st) {
        __nv_bfloat16* base = smg + st * 4 * GEMM_SZ;
#pragma unroll
        for (int it = 0; it < 2; ++it) {
            int idx = it * 256 + tid;           // 0..511
            int row = idx >> 2;
            int ch = (idx & 3) * 8;             // col (8 bf16 = 16B)
            int so = row * LDK + ch;
            size_t ga = (size_t)(bm + row) * K + k0 + ch;
            size_t gb = (size_t)(bn + row) * K + k0 + ch;
            cpa16(smem_u32(base + so), Ah + ga);
            cpa16(smem_u32(base + GEMM_SZ + so), Al + ga);
            cpa16(smem_u32(base + 2 * GEMM_SZ + so), Bh + gb);
            cpa16(smem_u32(base + 3 * GEMM_SZ + so), Bl + gb);
        }
    };

    const int nk = K / 32;
    load_stage(0, 0);
    cpa_commit();

    for (int i = 0; i < nk; ++i) {
        if (i + 1 < nk) {
            load_stage((i + 1) * 32, (i + 1) & 1);
            cpa_commit();
            cpa_wait<1>();
        } else {
            cpa_wait<0>();
        }
        __syncthreads();

        const __nv_bfloat16* base = smg + (i & 1) * 4 * GEMM_SZ;
        const __nv_bfloat16* sAh = base;
        const __nv_bfloat16* sAl = base + GEMM_SZ;
        const __nv_bfloat16* sBh = base + 2 * GEMM_SZ;
        const __nv_bfloat16* sBl = base + 3 * GEMM_SZ;

#pragma unroll
        for (int ks = 0; ks < 32; ks += 16) {
            uint32_t bhF[4][2], blF[4][2];
#pragma unroll
            for (int pair = 0; pair < 2; ++pair) {
                int atom = pair * 2 + (mat >> 1);
                int kc = ks + (mat & 1) * 8;
                int nrow = wn + atom * 8 + mrw;
                uint32_t r0, r1, r2, r3;
                ldmx4(smem_u32(&sBh[nrow * LDK + kc]), r0, r1, r2, r3);
                bhF[pair * 2][0] = r0; bhF[pair * 2][1] = r1;
                bhF[pair * 2 + 1][0] = r2; bhF[pair * 2 + 1][1] = r3;
                ldmx4(smem_u32(&sBl[nrow * LDK + kc]), r0, r1, r2, r3);
                blF[pair * 2][0] = r0; blF[pair * 2][1] = r1;
                blF[pair * 2 + 1][0] = r2; blF[pair * 2 + 1][1] = r3;
            }
#pragma unroll
            for (int am = 0; am < 4; ++am) {
                int arow = wm + am * 16 + (mat & 1) * 8 + mrw;
                int akc = ks + (mat >> 1) * 8;
                uint32_t ahF[4], alF[4];
                ldmx4(smem_u32(&sAh[arow * LDK + akc]), ahF[0], ahF[1], ahF[2], ahF[3]);
                ldmx4(smem_u32(&sAl[arow * LDK + akc]), alF[0], alF[1], alF[2], alF[3]);
#pragma unroll
                for (int an = 0; an < 4; ++an) {
                    mma_bf16(acc[am][an], ahF, bhF[an]);
                    mma_bf16(acc[am][an], ahF, blF[an]);
                    mma_bf16(acc[am][an], alF, bhF[an]);
                }
            }
        }
        __syncthreads();
    }

    // ---- epilogue ----
    const int gid = lane >> 2;
    const int tig = lane & 3;
#pragma unroll
    for (int am = 0; am < 4; ++am) {
#pragma unroll
        for (int an = 0; an < 4; ++an) {
            int m0 = bm + wm + am * 16 + gid;
            int m1 = m0 + 8;
            int n0 = bn + wn + an * 8 + tig * 2;
            float bs0 = bias[n0], bs1 = bias[n0 + 1];
            float v00 = acc[am][an][0] + bs0;
            float v01 = acc[am][an][1] + bs1;
            float v10 = acc[am][an][2] + bs0;
            float v11 = acc[am][an][3] + bs1;
            if (EPI == 0) {
                int hh = n0 >> 6, dh = n0 & 63;
                size_t i0 = (((size_t)((m0 >> 11) * NHEAD + hh) * SEQ) + (m0 & 2047)) * HDIM + dh;
                size_t i1 = (((size_t)((m1 >> 11) * NHEAD + hh) * SEQ) + (m1 & 2047)) * HDIM + dh;
                uint32_t hw, lw;
                split2(v00, v01, hw, lw);
                *reinterpret_cast<uint32_t*>(&outh[i0]) = hw;
                *reinterpret_cast<uint32_t*>(&outl[i0]) = lw;
                split2(v10, v11, hw, lw);
                *reinterpret_cast<uint32_t*>(&outh[i1]) = hw;
                *reinterpret_cast<uint32_t*>(&outl[i1]) = lw;
            } else if (EPI == 1) {
                size_t o0 = (size_t)m0 * N + n0;
                size_t o1 = (size_t)m1 * N + n0;
                float2 r0 = *reinterpret_cast<const float2*>(&res[o0]);
                float2 r1 = *reinterpret_cast<const float2*>(&res[o1]);
                float2 w0 = {v00 + r0.x, v01 + r0.y};
                float2 w1 = {v10 + r1.x, v11 + r1.y};
                *reinterpret_cast<float2*>(&outf[o0]) = w0;
                *reinterpret_cast<float2*>(&outf[o1]) = w1;
            } else {
                size_t o0 = (size_t)m0 * N + n0;
                size_t o1 = (size_t)m1 * N + n0;
                float g00 = 0.5f * v00 * (1.0f + erff(v00 * 0.70710678118654752f));
                float g01 = 0.5f * v01 * (1.0f + erff(v01 * 0.70710678118654752f));
                float g10 = 0.5f * v10 * (1.0f + erff(v10 * 0.70710678118654752f));
                float g11 = 0.5f * v11 * (1.0f + erff(v11 * 0.70710678118654752f));
                uint32_t hw, lw;
                split2(g00, g01, hw, lw);
                *reinterpret_cast<uint32_t*>(&outh[o0]) = hw;
                *reinterpret_cast<uint32_t*>(&outl[o0]) = lw;
                split2(g10, g11, hw, lw);
                *reinterpret_cast<uint32_t*>(&outh[o1]) = hw;
                *reinterpret_cast<uint32_t*>(&outl[o1]) = lw;
            }
        }
    }
}

// ================= tensor-core flash attention (pre-split bf16) ============
// grid (BH=32, SEQ/128=16), 256 threads (8 warps), 16 q rows/warp, 64-key tiles.
// V kept k-major; PV B-fragments via ldmatrix.trans. K/V double-buffered cp.async.
#define ALD 72
#define KVSZ (64 * ALD)                                  // elements per K/V array
#define ATTN_SMEM ((2 * 128 * ALD + 2 * 4 * KVSZ) * 2)   // 110592 bytes

__global__ __launch_bounds__(256, 2)
void attn_mma2(const __nv_bfloat16* __restrict__ qh, const __nv_bfloat16* __restrict__ ql,
               const __nv_bfloat16* __restrict__ kh, const __nv_bfloat16* __restrict__ kl,
               const __nv_bfloat16* __restrict__ vh, const __nv_bfloat16* __restrict__ vl,
               __nv_bfloat16* __restrict__ ctxh, __nv_bfloat16* __restrict__ ctxl) {
    extern __shared__ __nv_bfloat16 sm[];
    __nv_bfloat16* sQh = sm;                     // [128][ALD]
    __nv_bfloat16* sQl = sQh + 128 * ALD;
    __nv_bfloat16* stage = sQl + 128 * ALD;      // 2 x {Kh,Kl,Vh,Vl} [64][ALD]

    const int bh = blockIdx.x;
    const int qt = blockIdx.y;
    const int b = bh >> 3;
    const int h = bh & 7;
    const int tid = threadIdx.x;
    const int warp = tid >> 5;
    const int lane = tid & 31;
    const int mat = lane >> 3;
    const int mrw = lane & 7;
    const int gid = lane >> 2;
    const int tig = lane & 3;

    const size_t qoff = ((size_t)bh * SEQ + qt * 128) * HDIM;
    const size_t koff = (size_t)bh * SEQ * HDIM;

    auto load_kv = [&](int kt, int st) {
        const size_t toff = koff + (size_t)kt * 64 * HDIM;
        __nv_bfloat16* bs = stage + st * 4 * KVSZ;
#pragma unroll
        for (int it = 0; it < 2; ++it) {
            int idx = it * 256 + tid;      // 512 chunks per array
            int row = idx >> 3;            // kk
            int ch = (idx & 7) * 8;        // d
            int so = row * ALD + ch;
            size_t g = toff + row * HDIM + ch;
            cpa16(smem_u32(bs + so), kh + g);
            cpa16(smem_u32(bs + KVSZ + so), kl + g);
            cpa16(smem_u32(bs + 2 * KVSZ + so), vh + g);
            cpa16(smem_u32(bs + 3 * KVSZ + so), vl + g);
        }
    };

    // prefetch first K/V tile, then load Q (plain copies)
    load_kv(0, 0);
    cpa_commit();

#pragma unroll
    for (int it = 0; it < 4; ++it) {
        int idx = it * 256 + tid;         // 1024 chunks
        int row = idx >> 3;
        int ch = (idx & 7) * 8;
        int so = row * ALD + ch;
        *reinterpret_cast<uint4*>(&sQh[so]) =
            *reinterpret_cast<const uint4*>(&qh[qoff + row * HDIM + ch]);
        *reinterpret_cast<uint4*>(&sQl[so]) =
            *reinterpret_cast<const uint4*>(&ql[qoff + row * HDIM + ch]);
    }

    float o[8][4];
#pragma unroll
    for (int j = 0; j < 8; ++j)
#pragma unroll
        for (int c = 0; c < 4; ++c) o[j][c] = 0.0f;
    float m0 = -1e30f, m1 = -1e30f, l0r = 0.0f, l1r = 0.0f;

    const int NT = SEQ / 64;
    for (int kt = 0; kt < NT; ++kt) {
        if (kt + 1 < NT) {
            // buffer (kt+1)&1 was last read at iter kt-1; end-of-iter sync protects it
            load_kv(kt + 1, (kt + 1) & 1);
            cpa_commit();
            cpa_wait<1>();
        } else {
            cpa_wait<0>();
        }
        __syncthreads();

        const __nv_bfloat16* bs = stage + (kt & 1) * 4 * KVSZ;
        const __nv_bfloat16* sKh = bs;
        const __nv_bfloat16* sKl = bs + KVSZ;
        const __nv_bfloat16* sVh = bs + 2 * KVSZ;
        const __nv_bfloat16* sVl = bs + 3 * KVSZ;

        // ---- S = Q K^T : warp computes 16x64 ----
        float sa[8][4];
#pragma unroll
        for (int j = 0; j < 8; ++j)
#pragma unroll
            for (int c = 0; c < 4; ++c) sa[j][c] = 0.0f;

#pragma unroll
        for (int s = 0; s < 4; ++s) {
            int akc = 16 * s + (mat >> 1) * 8;
            int arow = 16 * warp + (mat & 1) * 8 + mrw;
            uint32_t qhF[4], qlF[4];
            ldmx4(smem_u32(&sQh[arow * ALD + akc]), qhF[0], qhF[1], qhF[2], qhF[3]);
            ldmx4(smem_u32(&sQl[arow * ALD + akc]), qlF[0], qlF[1], qlF[2], qlF[3]);
            uint32_t khF[8][2], klF[8][2];
#pragma unroll
            for (int pair = 0; pair < 4; ++pair) {
                int atom = pair * 2 + (mat >> 1);
                int kc = 16 * s + (mat & 1) * 8;
                int nrow = atom * 8 + mrw;
                uint32_t r0, r1, r2, r3;
                ldmx4(smem_u32(&sKh[nrow * ALD + kc]), r0, r1, r2, r3);
                khF[pair * 2][0] = r0; khF[pair * 2][1] = r1;
                khF[pair * 2 + 1][0] = r2; khF[pair * 2 + 1][1] = r3;
                ldmx4(smem_u32(&sKl[nrow * ALD + kc]), r0, r1, r2, r3);
                klF[pair * 2][0] = r0; klF[pair * 2][1] = r1;
                klF[pair * 2 + 1][0] = r2; klF[pair * 2 + 1][1] = r3;
            }
#pragma unroll
            for (int j = 0; j < 8; ++j) {
                mma_bf16(sa[j], qhF, khF[j]);
                mma_bf16(sa[j], qhF, klF[j]);
                mma_bf16(sa[j], qlF, khF[j]);
            }
        }

        // ---- online softmax ----
        float mx0 = -1e30f, mx1 = -1e30f;
#pragma unroll
        for (int j = 0; j < 8; ++j) {
            sa[j][0] *= 0.125f; sa[j][1] *= 0.125f;
            sa[j][2] *= 0.125f; sa[j][3] *= 0.125f;
            mx0 = fmaxf(mx0, fmaxf(sa[j][0], sa[j][1]));
            mx1 = fmaxf(mx1, fmaxf(sa[j][2], sa[j][3]));
        }
        mx0 = fmaxf(mx0, __shfl_xor_sync(0xffffffffu, mx0, 1));
        mx0 = fmaxf(mx0, __shfl_xor_sync(0xffffffffu, mx0, 2));
        mx1 = fmaxf(mx1, __shfl_xor_sync(0xffffffffu, mx1, 1));
        mx1 = fmaxf(mx1, __shfl_xor_sync(0xffffffffu, mx1, 2));
        float mn0 = fmaxf(m0, mx0), mn1 = fmaxf(m1, mx1);
        float f0 = __expf(m0 - mn0), f1 = __expf(m1 - mn1);

        float rs0 = 0.0f, rs1 = 0.0f;
        uint32_t ph2[8][2], pl2[8][2];
#pragma unroll
        for (int j = 0; j < 8; ++j) {
            float p0 = __expf(sa[j][0] - mn0);
            float p1 = __expf(sa[j][1] - mn0);
            float p2 = __expf(sa[j][2] - mn1);
            float p3 = __expf(sa[j][3] - mn1);
            rs0 += p0 + p1;
            rs1 += p2 + p3;
            split2(p0, p1, ph2[j][0], pl2[j][0]);
            split2(p2, p3, ph2[j][1], pl2[j][1]);
            o[j][0] *= f0; o[j][1] *= f0;
            o[j][2] *= f1; o[j][3] *= f1;
        }
        rs0 += __shfl_xor_sync(0xffffffffu, rs0, 1);
        rs0 += __shfl_xor_sync(0xffffffffu, rs0, 2);
        rs1 += __shfl_xor_sync(0xffffffffu, rs1, 1);
        rs1 += __shfl_xor_sync(0xffffffffu, rs1, 2);
        l0r = l0r * f0 + rs0;
        l1r = l1r * f1 + rs1;
        m0 = mn0; m1 = mn1;

        // ---- O += P V : B-fragments via ldmatrix.trans on k-major V ----
#pragma unroll
        for (int s = 0; s < 4; ++s) {
            uint32_t pah[4] = {ph2[2 * s][0], ph2[2 * s][1],
                               ph2[2 * s + 1][0], ph2[2 * s + 1][1]};
            uint32_t pal[4] = {pl2[2 * s][0], pl2[2 * s][1],
                               pl2[2 * s + 1][0], pl2[2 * s + 1][1]};
            uint32_t vhF[8][2], vlF[8][2];
#pragma unroll
            for (int pair = 0; pair < 4; ++pair) {
                // matrix m: d-atom = pair*2 + (m>>1), key-half = m&1 (same map as before)
                int krow = 16 * s + (mat & 1) * 8 + mrw;       // key row in V tile
                int dcol = (pair * 2 + (mat >> 1)) * 8;        // d column
                uint32_t r0, r1, r2, r3;
                ldmx4t(smem_u32(&sVh[krow * ALD + dcol]), r0, r1, r2, r3);
                vhF[pair * 2][0] = r0; vhF[pair * 2][1] = r1;
                vhF[pair * 2 + 1][0] = r2; vhF[pair * 2 + 1][1] = r3;
                ldmx4t(smem_u32(&sVl[krow * ALD + dcol]), r0, r1, r2, r3);
                vlF[pair * 2][0] = r0; vlF[pair * 2][1] = r1;
                vlF[pair * 2 + 1][0] = r2; vlF[pair * 2 + 1][1] = r3;
            }
#pragma unroll
            for (int j = 0; j < 8; ++j) {
                mma_bf16(o[j], pah, vhF[j]);
                mma_bf16(o[j], pah, vlF[j]);
                mma_bf16(o[j], pal, vhF[j]);
            }
        }
        __syncthreads();   // all warps done with this buffer before it is re-prefetched
    }

    // ---- epilogue: normalize, split, write ctx hi/lo [B,T,D] ----
    float inv0 = 1.0f / l0r;
    float inv1 = 1.0f / l1r;
    int t0 = qt * 128 + warp * 16 + gid;
    int t1 = t0 + 8;
#pragma unroll
    for (int j = 0; j < 8; ++j) {
        int col = h * HDIM + j * 8 + tig * 2;
        size_t i0 = ((size_t)(b * SEQ + t0)) * DMODEL + col;
        size_t i1 = ((size_t)(b * SEQ + t1)) * DMODEL + col;
        uint32_t hw, lw;
        split2(o[j][0] * inv0, o[j][1] * inv0, hw, lw);
        *reinterpret_cast<uint32_t*>(&ctxh[i0]) = hw;
        *reinterpret_cast<uint32_t*>(&ctxl[i0]) = lw;
        split2(o[j][2] * inv1, o[j][3] * inv1, hw, lw);
        *reinterpret_cast<uint32_t*>(&ctxh[i1]) = hw;
        *reinterpret_cast<uint32_t*>(&ctxl[i1]) = lw;
    }
}

// ---------------- LayerNorm (optionally emits split bf16 too) --------------
template <int SPLIT>
__global__ __launch_bounds__(128)
void ln_kernel(const float* __restrict__ in, const float* __restrict__ g,
               const float* __restrict__ beta, float* __restrict__ out,
               __nv_bfloat16* __restrict__ outh, __nv_bfloat16* __restrict__ outl) {
    __shared__ float red[8];
    const int row = blockIdx.x;
    const int tid = threadIdx.x;
    const int lane = tid & 31;
    const int wid = tid >> 5;

    float4 x4 = *reinterpret_cast<const float4*>(in + (size_t)row * DMODEL + tid * 4);
    float s = x4.x + x4.y + x4.z + x4.w;
#pragma unroll
    for (int off = 16; off; off >>= 1) s += __shfl_xor_sync(0xffffffffu, s, off);
    if (lane == 0) red[wid] = s;
    __syncthreads();
    float mean = (red[0] + red[1] + red[2] + red[3]) * (1.0f / DMODEL);

    float d0 = x4.x - mean, d1 = x4.y - mean, d2 = x4.z - mean, d3 = x4.w - mean;
    float sq = d0 * d0 + d1 * d1 + d2 * d2 + d3 * d3;
#pragma unroll
    for (int off = 16; off; off >>= 1) sq += __shfl_xor_sync(0xffffffffu, sq, off);
    if (lane == 0) red[4 + wid] = sq;
    __syncthreads();
    float var = (red[4] + red[5] + red[6] + red[7]) * (1.0f / DMODEL);
    float rstd = rsqrtf(var + 1e-5f);

    float4 g4 = *reinterpret_cast<const float4*>(g + tid * 4);
    float4 b4 = *reinterpret_cast<const float4*>(beta + tid * 4);
    float4 y;
    y.x = d0 * rstd * g4.x + b4.x;
    y.y = d1 * rstd * g4.y + b4.y;
    y.z = d2 * rstd * g4.z + b4.z;
    y.w = d3 * rstd * g4.w + b4.w;
    *reinterpret_cast<float4*>(out + (size_t)row * DMODEL + tid * 4) = y;
    if (SPLIT) {
        size_t o0 = (size_t)row * DMODEL + tid * 4;
        uint32_t h0, l0, h1, l1;
        split2(y.x, y.y, h0, l0);
        split2(y.z, y.w, h1, l1);
        *reinterpret_cast<uint32_t*>(&outh[o0])     = h0;
        *reinterpret_cast<uint32_t*>(&outh[o0 + 2]) = h1;
        *reinterpret_cast<uint32_t*>(&outl[o0])     = l0;
        *reinterpret_cast<uint32_t*>(&outl[o0 + 2]) = l1;
    }
}

// ---------------- host-side orchestration ---------------------------------
extern "C" void kernel_launch(void* const* d_in, const int* in_sizes, int n_in,
                              void* d_out, int out_size) {
    const float* src = (const float*)d_in[0];
    const float* Wq = (const float*)d_in[1];
    const float* bq = (const float*)d_in[2];
    const float* Wk = (const float*)d_in[3];
    const float* bk = (const float*)d_in[4];
    const float* Wv = (const float*)d_in[5];
    const float* bv = (const float*)d_in[6];
    const float* Wo = (const float*)d_in[7];
    const float* bo = (const float*)d_in[8];
    const float* W1 = (const float*)d_in[9];
    const float* b1 = (const float*)d_in[10];
    const float* W2 = (const float*)d_in[11];
    const float* b2 = (const float*)d_in[12];
    const float* g1 = (const float*)d_in[13];
    const float* be1 = (const float*)d_in[14];
    const float* g2 = (const float*)d_in[15];
    const float* be2 = (const float*)d_in[16];
    float* outp = (float*)d_out;

    // resolve scratch symbols
    void* p;
#define SYM(name) cudaGetSymbolAddress(&p, name)
    __nv_bfloat16 *srch, *srcl, *qh, *ql, *kh, *kl, *vh, *vl;
    __nv_bfloat16 *ctxh, *ctxl, *x1h, *x1l, *hidh, *hidl, *wh, *wl;
    float *TMP, *X1;
    SYM(s_srch); srch = (__nv_bfloat16*)p;
    SYM(s_srcl); srcl = (__nv_bfloat16*)p;
    SYM(s_qh); qh = (__nv_bfloat16*)p;
    SYM(s_ql); ql = (__nv_bfloat16*)p;
    SYM(s_kh); kh = (__nv_bfloat16*)p;
    SYM(s_kl); kl = (__nv_bfloat16*)p;
    SYM(s_vh); vh = (__nv_bfloat16*)p;
    SYM(s_vl); vl = (__nv_bfloat16*)p;
    SYM(s_ctxh); ctxh = (__nv_bfloat16*)p;
    SYM(s_ctxl); ctxl = (__nv_bfloat16*)p;
    SYM(s_x1h); x1h = (__nv_bfloat16*)p;
    SYM(s_x1l); x1l = (__nv_bfloat16*)p;
    SYM(s_hidh); hidh = (__nv_bfloat16*)p;
    SYM(s_hidl); hidl = (__nv_bfloat16*)p;
    SYM(s_wh); wh = (__nv_bfloat16*)p;
    SYM(s_wl); wl = (__nv_bfloat16*)p;
    SYM(g_tmp); TMP = (float*)p;
    SYM(g_x1); X1 = (float*)p;
#undef SYM

    cudaFuncSetAttribute(attn_mma2, cudaFuncAttributeMaxDynamicSharedMemorySize,
                         ATTN_SMEM);
    cudaFuncSetAttribute(gemm_mma2<0>, cudaFuncAttributeMaxDynamicSharedMemorySize,
                         GEMM_SMEM);
    cudaFuncSetAttribute(gemm_mma2<1>, cudaFuncAttributeMaxDynamicSharedMemorySize,
                         GEMM_SMEM);
    cudaFuncSetAttribute(gemm_mma2<2>, cudaFuncAttributeMaxDynamicSharedMemorySize,
                         GEMM_SMEM);

    dim3 blk(256);
    dim3 grid_d(DMODEL / 128, MROWS / 128);   // (4, 64)
    dim3 grid_ff(DFF / 128, MROWS / 128);     // (16, 64)

    // ---- split src + weights ----
    split_kernel<<<ACT / 4 / 256, 256>>>(src, srch, srcl, ACT / 4);
    split_kernel<<<WSQ / 4 / 256, 256>>>(Wq, wh + OFF_WQ, wl + OFF_WQ, WSQ / 4);
    split_kernel<<<WSQ / 4 / 256, 256>>>(Wk, wh + OFF_WK, wl + OFF_WK, WSQ / 4);
    split_kernel<<<WSQ / 4 / 256, 256>>>(Wv, wh + OFF_WV, wl + OFF_WV, WSQ / 4);
    split_kernel<<<WSQ / 4 / 256, 256>>>(Wo, wh + OFF_WO, wl + OFF_WO, WSQ / 4);
    split_kernel<<<WFF / 4 / 256, 256>>>(W1, wh + OFF_W1, wl + OFF_W1, WFF / 4);
    split_kernel<<<WFF / 4 / 256, 256>>>(W2, wh + OFF_W2, wl + OFF_W2, WFF / 4);

    // ---- Q/K/V projections -> split [BH,T,64] ----
    gemm_mma2<0><<<grid_d, blk, GEMM_SMEM>>>(srch, srcl, wh + OFF_WQ, wl + OFF_WQ,
                                             bq, nullptr, nullptr, qh, ql,
                                             MROWS, DMODEL, DMODEL);
    gemm_mma2<0><<<grid_d, blk, GEMM_SMEM>>>(srch, srcl, wh + OFF_WK, wl + OFF_WK,
                                             bk, nullptr, nullptr, kh, kl,
                                             MROWS, DMODEL, DMODEL);
    gemm_mma2<0><<<grid_d, blk, GEMM_SMEM>>>(srch, srcl, wh + OFF_WV, wl + OFF_WV,
                                             bv, nullptr, nullptr, vh, vl,
                                             MROWS, DMODEL, DMODEL);

    // ---- attention -> split ctx [B,T,D] ----
    attn_mma2<<<dim3(BATCH * NHEAD, SEQ / 128), blk, ATTN_SMEM>>>(
        qh, ql, kh, kl, vh, vl, ctxh, ctxl);

    // ---- O-proj + bias + residual(src) -> TMP ; LN1 -> X1 fp32 + split ----
    gemm_mma2<1><<<grid_d, blk, GEMM_SMEM>>>(ctxh, ctxl, wh + OFF_WO, wl + OFF_WO,
                                             bo, src, TMP, nullptr, nullptr,
                                             MROWS, DMODEL, DMODEL);
    ln_kernel<1><<<MROWS, 128>>>(TMP, g1, be1, X1, x1h, x1l);

    // ---- FFN1 + GELU -> split HID ----
    gemm_mma2<2><<<grid_ff, blk, GEMM_SMEM>>>(x1h, x1l, wh + OFF_W1, wl + OFF_W1,
                                              b1, nullptr, nullptr, hidh, hidl,
                                              MROWS, DFF, DMODEL);

    // ---- FFN2 + bias + residual(X1) -> TMP ; LN2 -> out ----
    gemm_mma2<1><<<grid_d, blk, GEMM_SMEM>>>(hidh, hidl, wh + OFF_W2, wl + OFF_W2,
                                             b2, X1, TMP, nullptr, nullptr,
                                             MROWS, DMODEL, DFF);
    ln_kernel<0><<<MROWS, 128>>>(TMP, g2, be2, outp, nullptr, nullptr);
}

// round 13
// speedup vs baseline: 3.6500x; 1.0905x over previous
#include <cuda_runtime.h>
#include <cuda_bf16.h>
#include <math.h>
#include <stdint.h>

// Problem constants
#define BATCH 4
#define SEQ   2048
#define DMODEL 512
#define NHEAD 8
#define HDIM  64
#define DFF   2048
#define MROWS (BATCH * SEQ)   // 8192

#define ACT   (MROWS * DMODEL)        // 4,194,304
#define WSQ   (DMODEL * DMODEL)       // 262,144
#define WFF   (DFF * DMODEL)          // 1,048,576
#define WTOT  (4 * WSQ + 2 * WFF)     // 3,145,728

// weight offsets in combined split-weight buffers
#define OFF_WQ 0
#define OFF_WK (1 * WSQ)
#define OFF_WV (2 * WSQ)
#define OFF_WO (3 * WSQ)
#define OFF_W1 (4 * WSQ)
#define OFF_W2 (4 * WSQ + WFF)

// ---------------- scratch (static device arrays; no allocation allowed) ----
__device__ __nv_bfloat16 s_srch[ACT], s_srcl[ACT];
__device__ __nv_bfloat16 s_qh[ACT], s_ql[ACT];
__device__ __nv_bfloat16 s_kh[ACT], s_kl[ACT];
__device__ __nv_bfloat16 s_vh[ACT], s_vl[ACT];
__device__ __nv_bfloat16 s_ctxh[ACT], s_ctxl[ACT];
__device__ __nv_bfloat16 s_x1h[ACT], s_x1l[ACT];
__device__ __nv_bfloat16 s_hidh[MROWS * DFF], s_hidl[MROWS * DFF];
__device__ __nv_bfloat16 s_wh[WTOT], s_wl[WTOT];
__device__ float g_tmp[ACT];     // pre-LN fp32
__device__ float g_x1[ACT];      // post-LN1 fp32 (residual for FFN2)

// ---------------- common helpers -------------------------------------------
__device__ __forceinline__ uint32_t smem_u32(const void* p) {
    return (uint32_t)__cvta_generic_to_shared(p);
}

__device__ __forceinline__ void ldmx4(uint32_t addr, uint32_t& r0, uint32_t& r1,
                                      uint32_t& r2, uint32_t& r3) {
    asm volatile("ldmatrix.sync.aligned.m8n8.x4.shared.b16 {%0,%1,%2,%3}, [%4];"
                 : "=r"(r0), "=r"(r1), "=r"(r2), "=r"(r3) : "r"(addr));
}

__device__ __forceinline__ void ldmx4t(uint32_t addr, uint32_t& r0, uint32_t& r1,
                                       uint32_t& r2, uint32_t& r3) {
    asm volatile("ldmatrix.sync.aligned.m8n8.x4.trans.shared.b16 {%0,%1,%2,%3}, [%4];"
                 : "=r"(r0), "=r"(r1), "=r"(r2), "=r"(r3) : "r"(addr));
}

__device__ __forceinline__ void mma_bf16(float* c, const uint32_t* a, const uint32_t* b) {
    asm volatile(
        "mma.sync.aligned.m16n8k16.row.col.f32.bf16.bf16.f32 "
        "{%0,%1,%2,%3}, {%4,%5,%6,%7}, {%8,%9}, {%0,%1,%2,%3};"
        : "+f"(c[0]), "+f"(c[1]), "+f"(c[2]), "+f"(c[3])
        : "r"(a[0]), "r"(a[1]), "r"(a[2]), "r"(a[3]), "r"(b[0]), "r"(b[1]));
}

__device__ __forceinline__ void split2(float x, float y, uint32_t& hi, uint32_t& lo) {
    __nv_bfloat16 xh = __float2bfloat16_rn(x);
    __nv_bfloat16 yh = __float2bfloat16_rn(y);
    __nv_bfloat16 xl = __float2bfloat16_rn(x - __bfloat162float(xh));
    __nv_bfloat16 yl = __float2bfloat16_rn(y - __bfloat162float(yh));
    __nv_bfloat162 h2(xh, yh), l2(xl, yl);
    hi = *reinterpret_cast<uint32_t*>(&h2);
    lo = *reinterpret_cast<uint32_t*>(&l2);
}

__device__ __forceinline__ void cpa16(uint32_t dst, const void* src) {
    asm volatile("cp.async.cg.shared.global [%0], [%1], 16;\n" ::"r"(dst), "l"(src));
}
__device__ __forceinline__ void cpa_commit() {
    asm volatile("cp.async.commit_group;\n" ::);
}
template <int N>
__device__ __forceinline__ void cpa_wait() {
    asm volatile("cp.async.wait_group %0;\n" ::"n"(N));
}

// ---------------- split pass: fp32 -> bf16 hi/lo ---------------------------
__global__ __launch_bounds__(256)
void split_kernel(const float* __restrict__ in, __nv_bfloat16* __restrict__ hi,
                  __nv_bfloat16* __restrict__ lo, int n4) {
    int i = blockIdx.x * blockDim.x + threadIdx.x;
    if (i < n4) {
        float4 v = reinterpret_cast<const float4*>(in)[i];
        uint32_t h0, l0, h1, l1;
        split2(v.x, v.y, h0, l0);
        split2(v.z, v.w, h1, l1);
        reinterpret_cast<uint32_t*>(hi)[i * 2]     = h0;
        reinterpret_cast<uint32_t*>(hi)[i * 2 + 1] = h1;
        reinterpret_cast<uint32_t*>(lo)[i * 2]     = l0;
        reinterpret_cast<uint32_t*>(lo)[i * 2 + 1] = l1;
    }
}

// ================= pre-split bf16 tensor-core GEMM =========================
// C = A (MxK) * B^T, A/B given as bf16 hi/lo arrays. 3 MMAs (hh+hl+lh).
// Block 128x128, BK=32, 256 threads (2m x 4n warps), cp.async double-buffered.
// __launch_bounds__(256,2): force <=128 regs so 2 CTAs/SM (smem 2x80KB fits).
#define LDK 40
#define GEMM_SZ (128 * LDK)                 // elements per smem array
#define GEMM_SMEM (2 * 4 * GEMM_SZ * 2)     // 81920 bytes

template <int EPI>
__global__ __launch_bounds__(256, 2)
void gemm_mma2(const __nv_bfloat16* __restrict__ Ah, const __nv_bfloat16* __restrict__ Al,
               const __nv_bfloat16* __restrict__ Bh, const __nv_bfloat16* __restrict__ Bl,
               const float* __restrict__ bias, const float* __restrict__ res,
               float* __restrict__ outf, __nv_bfloat16* __restrict__ outh,
               __nv_bfloat16* __restrict__ outl, int M, int N, int K) {
    extern __shared__ __nv_bfloat16 smg[];

    const int tid = threadIdx.x;
    const int warp = tid >> 5;
    const int lane = tid & 31;
    const int wm = (warp & 1) * 64;
    const int wn = (warp >> 1) * 32;
    const int bm = blockIdx.y * 128;
    const int bn = blockIdx.x * 128;
    const int mat = lane >> 3;
    const int mrw = lane & 7;

    float acc[4][4][4];
#pragma unroll
    for (int i = 0; i < 4; ++i)
#pragma unroll
        for (int j = 0; j < 4; ++j)
#pragma unroll
            for (int c = 0; c < 4; ++c) acc[i][j][c] = 0.0f;

    auto load_stage = [&](int k0, int st) {
        __nv_bfloat16* base = smg + st * 4 * GEMM_SZ;
#pragma unroll
        for (int it = 0; it < 2; ++it) {
            int idx = it * 256 + tid;           // 0..511
            int row = idx >> 2;
            int ch = (idx & 3) * 8;             // col (8 bf16 = 16B)
            int so = row * LDK + ch;
            size_t ga = (size_t)(bm + row) * K + k0 + ch;
            size_t gb = (size_t)(bn + row) * K + k0 + ch;
            cpa16(smem_u32(base + so), Ah + ga);
            cpa16(smem_u32(base + GEMM_SZ + so), Al + ga);
            cpa16(smem_u32(base + 2 * GEMM_SZ + so), Bh + gb);
            cpa16(smem_u32(base + 3 * GEMM_SZ + so), Bl + gb);
        }
    };

    const int nk = K / 32;
    load_stage(0, 0);
    cpa_commit();

    for (int i = 0; i < nk; ++i) {
        if (i + 1 < nk) {
            load_stage((i + 1) * 32, (i + 1) & 1);
            cpa_commit();
            cpa_wait<1>();
        } else {
            cpa_wait<0>();
        }
        __syncthreads();

        const __nv_bfloat16* base = smg + (i & 1) * 4 * GEMM_SZ;
        const __nv_bfloat16* sAh = base;
        const __nv_bfloat16* sAl = base + GEMM_SZ;
        const __nv_bfloat16* sBh = base + 2 * GEMM_SZ;
        const __nv_bfloat16* sBl = base + 3 * GEMM_SZ;

#pragma unroll
        for (int ks = 0; ks < 32; ks += 16) {
            uint32_t bhF[4][2], blF[4][2];
#pragma unroll
            for (int pair = 0; pair < 2; ++pair) {
                int atom = pair * 2 + (mat >> 1);
                int kc = ks + (mat & 1) * 8;
                int nrow = wn + atom * 8 + mrw;
                uint32_t r0, r1, r2, r3;
                ldmx4(smem_u32(&sBh[nrow * LDK + kc]), r0, r1, r2, r3);
                bhF[pair * 2][0] = r0; bhF[pair * 2][1] = r1;
                bhF[pair * 2 + 1][0] = r2; bhF[pair * 2 + 1][1] = r3;
                ldmx4(smem_u32(&sBl[nrow * LDK + kc]), r0, r1, r2, r3);
                blF[pair * 2][0] = r0; blF[pair * 2][1] = r1;
                blF[pair * 2 + 1][0] = r2; blF[pair * 2 + 1][1] = r3;
            }
#pragma unroll
            for (int am = 0; am < 4; ++am) {
                int arow = wm + am * 16 + (mat & 1) * 8 + mrw;
                int akc = ks + (mat >> 1) * 8;
                uint32_t ahF[4], alF[4];
                ldmx4(smem_u32(&sAh[arow * LDK + akc]), ahF[0], ahF[1], ahF[2], ahF[3]);
                ldmx4(smem_u32(&sAl[arow * LDK + akc]), alF[0], alF[1], alF[2], alF[3]);
#pragma unroll
                for (int an = 0; an < 4; ++an) {
                    mma_bf16(acc[am][an], ahF, bhF[an]);
                    mma_bf16(acc[am][an], ahF, blF[an]);
                    mma_bf16(acc[am][an], alF, bhF[an]);
                }
            }
        }
        __syncthreads();
    }

    // ---- epilogue ----
    const int gid = lane >> 2;
    const int tig = lane & 3;
#pragma unroll
    for (int am = 0; am < 4; ++am) {
#pragma unroll
        for (int an = 0; an < 4; ++an) {
            int m0 = bm + wm + am * 16 + gid;
            int m1 = m0 + 8;
            int n0 = bn + wn + an * 8 + tig * 2;
            float bs0 = bias[n0], bs1 = bias[n0 + 1];
            float v00 = acc[am][an][0] + bs0;
            float v01 = acc[am][an][1] + bs1;
            float v10 = acc[am][an][2] + bs0;
            float v11 = acc[am][an][3] + bs1;
            if (EPI == 0) {
                int hh = n0 >> 6, dh = n0 & 63;
                size_t i0 = (((size_t)((m0 >> 11) * NHEAD + hh) * SEQ) + (m0 & 2047)) * HDIM + dh;
                size_t i1 = (((size_t)((m1 >> 11) * NHEAD + hh) * SEQ) + (m1 & 2047)) * HDIM + dh;
                uint32_t hw, lw;
                split2(v00, v01, hw, lw);
                *reinterpret_cast<uint32_t*>(&outh[i0]) = hw;
                *reinterpret_cast<uint32_t*>(&outl[i0]) = lw;
                split2(v10, v11, hw, lw);
                *reinterpret_cast<uint32_t*>(&outh[i1]) = hw;
                *reinterpret_cast<uint32_t*>(&outl[i1]) = lw;
            } else if (EPI == 1) {
                size_t o0 = (size_t)m0 * N + n0;
                size_t o1 = (size_t)m1 * N + n0;
                float2 r0 = *reinterpret_cast<const float2*>(&res[o0]);
                float2 r1 = *reinterpret_cast<const float2*>(&res[o1]);
                float2 w0 = {v00 + r0.x, v01 + r0.y};
                float2 w1 = {v10 + r1.x, v11 + r1.y};
                *reinterpret_cast<float2*>(&outf[o0]) = w0;
                *reinterpret_cast<float2*>(&outf[o1]) = w1;
            } else {
                size_t o0 = (size_t)m0 * N + n0;
                size_t o1 = (size_t)m1 * N + n0;
                float g00 = 0.5f * v00 * (1.0f + erff(v00 * 0.70710678118654752f));
                float g01 = 0.5f * v01 * (1.0f + erff(v01 * 0.70710678118654752f));
                float g10 = 0.5f * v10 * (1.0f + erff(v10 * 0.70710678118654752f));
                float g11 = 0.5f * v11 * (1.0f + erff(v11 * 0.70710678118654752f));
                uint32_t hw, lw;
                split2(g00, g01, hw, lw);
                *reinterpret_cast<uint32_t*>(&outh[o0]) = hw;
                *reinterpret_cast<uint32_t*>(&outl[o0]) = lw;
                split2(g10, g11, hw, lw);
                *reinterpret_cast<uint32_t*>(&outh[o1]) = hw;
                *reinterpret_cast<uint32_t*>(&outl[o1]) = lw;
            }
        }
    }
}

// ================= tensor-core flash attention (pre-split bf16) ============
// grid (SEQ/128=16, BH=32) -- qt-major so consecutive CTAs share a head's K/V
// stream in L2. 256 threads (8 warps), 16 q rows/warp, 64-key tiles.
// V k-major; PV B-fragments via ldmatrix.trans. K/V double-buffered cp.async.
#define ALD 72
#define KVSZ (64 * ALD)                                  // elements per K/V array
#define ATTN_SMEM ((2 * 128 * ALD + 2 * 4 * KVSZ) * 2)   // 110592 bytes

__global__ __launch_bounds__(256, 2)
void attn_mma2(const __nv_bfloat16* __restrict__ qh, const __nv_bfloat16* __restrict__ ql,
               const __nv_bfloat16* __restrict__ kh, const __nv_bfloat16* __restrict__ kl,
               const __nv_bfloat16* __restrict__ vh, const __nv_bfloat16* __restrict__ vl,
               __nv_bfloat16* __restrict__ ctxh, __nv_bfloat16* __restrict__ ctxl) {
    extern __shared__ __nv_bfloat16 sm[];
    __nv_bfloat16* sQh = sm;                     // [128][ALD]
    __nv_bfloat16* sQl = sQh + 128 * ALD;
    __nv_bfloat16* stage = sQl + 128 * ALD;      // 2 x {Kh,Kl,Vh,Vl} [64][ALD]

    const int qt = blockIdx.x;
    const int bh = blockIdx.y;
    const int b = bh >> 3;
    const int h = bh & 7;
    const int tid = threadIdx.x;
    const int warp = tid >> 5;
    const int lane = tid & 31;
    const int mat = lane >> 3;
    const int mrw = lane & 7;
    const int gid = lane >> 2;
    const int tig = lane & 3;

    const size_t qoff = ((size_t)bh * SEQ + qt * 128) * HDIM;
    const size_t koff = (size_t)bh * SEQ * HDIM;

    auto load_kv = [&](int kt, int st) {
        const size_t toff = koff + (size_t)kt * 64 * HDIM;
        __nv_bfloat16* bs = stage + st * 4 * KVSZ;
#pragma unroll
        for (int it = 0; it < 2; ++it) {
            int idx = it * 256 + tid;      // 512 chunks per array
            int row = idx >> 3;            // kk
            int ch = (idx & 7) * 8;        // d
            int so = row * ALD + ch;
            size_t g = toff + row * HDIM + ch;
            cpa16(smem_u32(bs + so), kh + g);
            cpa16(smem_u32(bs + KVSZ + so), kl + g);
            cpa16(smem_u32(bs + 2 * KVSZ + so), vh + g);
            cpa16(smem_u32(bs + 3 * KVSZ + so), vl + g);
        }
    };

    // prefetch first K/V tile, then load Q (plain copies)
    load_kv(0, 0);
    cpa_commit();

#pragma unroll
    for (int it = 0; it < 4; ++it) {
        int idx = it * 256 + tid;         // 1024 chunks
        int row = idx >> 3;
        int ch = (idx & 7) * 8;
        int so = row * ALD + ch;
        *reinterpret_cast<uint4*>(&sQh[so]) =
            *reinterpret_cast<const uint4*>(&qh[qoff + row * HDIM + ch]);
        *reinterpret_cast<uint4*>(&sQl[so]) =
            *reinterpret_cast<const uint4*>(&ql[qoff + row * HDIM + ch]);
    }

    float o[8][4];
#pragma unroll
    for (int j = 0; j < 8; ++j)
#pragma unroll
        for (int c = 0; c < 4; ++c) o[j][c] = 0.0f;
    float m0 = -1e30f, m1 = -1e30f, l0r = 0.0f, l1r = 0.0f;

    const int NT = SEQ / 64;
    for (int kt = 0; kt < NT; ++kt) {
        if (kt + 1 < NT) {
            load_kv(kt + 1, (kt + 1) & 1);
            cpa_commit();
            cpa_wait<1>();
        } else {
            cpa_wait<0>();
        }
        __syncthreads();

        const __nv_bfloat16* bs = stage + (kt & 1) * 4 * KVSZ;
        const __nv_bfloat16* sKh = bs;
        const __nv_bfloat16* sKl = bs + KVSZ;
        const __nv_bfloat16* sVh = bs + 2 * KVSZ;
        const __nv_bfloat16* sVl = bs + 3 * KVSZ;

        // ---- S = Q K^T : warp computes 16x64 ----
        float sa[8][4];
#pragma unroll
        for (int j = 0; j < 8; ++j)
#pragma unroll
            for (int c = 0; c < 4; ++c) sa[j][c] = 0.0f;

#pragma unroll
        for (int s = 0; s < 4; ++s) {
            int akc = 16 * s + (mat >> 1) * 8;
            int arow = 16 * warp + (mat & 1) * 8 + mrw;
            uint32_t qhF[4], qlF[4];
            ldmx4(smem_u32(&sQh[arow * ALD + akc]), qhF[0], qhF[1], qhF[2], qhF[3]);
            ldmx4(smem_u32(&sQl[arow * ALD + akc]), qlF[0], qlF[1], qlF[2], qlF[3]);
            uint32_t khF[8][2], klF[8][2];
#pragma unroll
            for (int pair = 0; pair < 4; ++pair) {
                int atom = pair * 2 + (mat >> 1);
                int kc = 16 * s + (mat & 1) * 8;
                int nrow = atom * 8 + mrw;
                uint32_t r0, r1, r2, r3;
                ldmx4(smem_u32(&sKh[nrow * ALD + kc]), r0, r1, r2, r3);
                khF[pair * 2][0] = r0; khF[pair * 2][1] = r1;
                khF[pair * 2 + 1][0] = r2; khF[pair * 2 + 1][1] = r3;
                ldmx4(smem_u32(&sKl[nrow * ALD + kc]), r0, r1, r2, r3);
                klF[pair * 2][0] = r0; klF[pair * 2][1] = r1;
                klF[pair * 2 + 1][0] = r2; klF[pair * 2 + 1][1] = r3;
            }
#pragma unroll
            for (int j = 0; j < 8; ++j) {
                mma_bf16(sa[j], qhF, khF[j]);
                mma_bf16(sa[j], qhF, klF[j]);
                mma_bf16(sa[j], qlF, khF[j]);
            }
        }

        // ---- online softmax ----
        float mx0 = -1e30f, mx1 = -1e30f;
#pragma unroll
        for (int j = 0; j < 8; ++j) {
            sa[j][0] *= 0.125f; sa[j][1] *= 0.125f;
            sa[j][2] *= 0.125f; sa[j][3] *= 0.125f;
            mx0 = fmaxf(mx0, fmaxf(sa[j][0], sa[j][1]));
            mx1 = fmaxf(mx1, fmaxf(sa[j][2], sa[j][3]));
        }
        mx0 = fmaxf(mx0, __shfl_xor_sync(0xffffffffu, mx0, 1));
        mx0 = fmaxf(mx0, __shfl_xor_sync(0xffffffffu, mx0, 2));
        mx1 = fmaxf(mx1, __shfl_xor_sync(0xffffffffu, mx1, 1));
        mx1 = fmaxf(mx1, __shfl_xor_sync(0xffffffffu, mx1, 2));
        float mn0 = fmaxf(m0, mx0), mn1 = fmaxf(m1, mx1);
        float f0 = __expf(m0 - mn0), f1 = __expf(m1 - mn1);

        float rs0 = 0.0f, rs1 = 0.0f;
        uint32_t ph2[8][2], pl2[8][2];
#pragma unroll
        for (int j = 0; j < 8; ++j) {
            float p0 = __expf(sa[j][0] - mn0);
            float p1 = __expf(sa[j][1] - mn0);
            float p2 = __expf(sa[j][2] - mn1);
            float p3 = __expf(sa[j][3] - mn1);
            rs0 += p0 + p1;
            rs1 += p2 + p3;
            split2(p0, p1, ph2[j][0], pl2[j][0]);
            split2(p2, p3, ph2[j][1], pl2[j][1]);
            o[j][0] *= f0; o[j][1] *= f0;
            o[j][2] *= f1; o[j][3] *= f1;
        }
        rs0 += __shfl_xor_sync(0xffffffffu, rs0, 1);
        rs0 += __shfl_xor_sync(0xffffffffu, rs0, 2);
        rs1 += __shfl_xor_sync(0xffffffffu, rs1, 1);
        rs1 += __shfl_xor_sync(0xffffffffu, rs1, 2);
        l0r = l0r * f0 + rs0;
        l1r = l1r * f1 + rs1;
        m0 = mn0; m1 = mn1;

        // ---- O += P V : B-fragments via ldmatrix.trans on k-major V ----
#pragma unroll
        for (int s = 0; s < 4; ++s) {
            uint32_t pah[4] = {ph2[2 * s][0], ph2[2 * s][1],
                               ph2[2 * s + 1][0], ph2[2 * s + 1][1]};
            uint32_t pal[4] = {pl2[2 * s][0], pl2[2 * s][1],
                               pl2[2 * s + 1][0], pl2[2 * s + 1][1]};
            uint32_t vhF[8][2], vlF[8][2];
#pragma unroll
            for (int pair = 0; pair < 4; ++pair) {
                int krow = 16 * s + (mat & 1) * 8 + mrw;       // key row in V tile
                int dcol = (pair * 2 + (mat >> 1)) * 8;        // d column
                uint32_t r0, r1, r2, r3;
                ldmx4t(smem_u32(&sVh[krow * ALD + dcol]), r0, r1, r2, r3);
                vhF[pair * 2][0] = r0; vhF[pair * 2][1] = r1;
                vhF[pair * 2 + 1][0] = r2; vhF[pair * 2 + 1][1] = r3;
                ldmx4t(smem_u32(&sVl[krow * ALD + dcol]), r0, r1, r2, r3);
                vlF[pair * 2][0] = r0; vlF[pair * 2][1] = r1;
                vlF[pair * 2 + 1][0] = r2; vlF[pair * 2 + 1][1] = r3;
            }
#pragma unroll
            for (int j = 0; j < 8; ++j) {
                mma_bf16(o[j], pah, vhF[j]);
                mma_bf16(o[j], pah, vlF[j]);
                mma_bf16(o[j], pal, vhF[j]);
            }
        }
        __syncthreads();   // all warps done with this buffer before it is re-prefetched
    }

    // ---- epilogue: normalize, split, write ctx hi/lo [B,T,D] ----
    float inv0 = 1.0f / l0r;
    float inv1 = 1.0f / l1r;
    int t0 = qt * 128 + warp * 16 + gid;
    int t1 = t0 + 8;
#pragma unroll
    for (int j = 0; j < 8; ++j) {
        int col = h * HDIM + j * 8 + tig * 2;
        size_t i0 = ((size_t)(b * SEQ + t0)) * DMODEL + col;
        size_t i1 = ((size_t)(b * SEQ + t1)) * DMODEL + col;
        uint32_t hw, lw;
        split2(o[j][0] * inv0, o[j][1] * inv0, hw, lw);
        *reinterpret_cast<uint32_t*>(&ctxh[i0]) = hw;
        *reinterpret_cast<uint32_t*>(&ctxl[i0]) = lw;
        split2(o[j][2] * inv1, o[j][3] * inv1, hw, lw);
        *reinterpret_cast<uint32_t*>(&ctxh[i1]) = hw;
        *reinterpret_cast<uint32_t*>(&ctxl[i1]) = lw;
    }
}

// ---------------- LayerNorm (optionally emits split bf16 too) --------------
template <int SPLIT>
__global__ __launch_bounds__(128)
void ln_kernel(const float* __restrict__ in, const float* __restrict__ g,
               const float* __restrict__ beta, float* __restrict__ out,
               __nv_bfloat16* __restrict__ outh, __nv_bfloat16* __restrict__ outl) {
    __shared__ float red[8];
    const int row = blockIdx.x;
    const int tid = threadIdx.x;
    const int lane = tid & 31;
    const int wid = tid >> 5;

    float4 x4 = *reinterpret_cast<const float4*>(in + (size_t)row * DMODEL + tid * 4);
    float s = x4.x + x4.y + x4.z + x4.w;
#pragma unroll
    for (int off = 16; off; off >>= 1) s += __shfl_xor_sync(0xffffffffu, s, off);
    if (lane == 0) red[wid] = s;
    __syncthreads();
    float mean = (red[0] + red[1] + red[2] + red[3]) * (1.0f / DMODEL);

    float d0 = x4.x - mean, d1 = x4.y - mean, d2 = x4.z - mean, d3 = x4.w - mean;
    float sq = d0 * d0 + d1 * d1 + d2 * d2 + d3 * d3;
#pragma unroll
    for (int off = 16; off; off >>= 1) sq += __shfl_xor_sync(0xffffffffu, sq, off);
    if (lane == 0) red[4 + wid] = sq;
    __syncthreads();
    float var = (red[4] + red[5] + red[6] + red[7]) * (1.0f / DMODEL);
    float rstd = rsqrtf(var + 1e-5f);

    float4 g4 = *reinterpret_cast<const float4*>(g + tid * 4);
    float4 b4 = *reinterpret_cast<const float4*>(beta + tid * 4);
    float4 y;
    y.x = d0 * rstd * g4.x + b4.x;
    y.y = d1 * rstd * g4.y + b4.y;
    y.z = d2 * rstd * g4.z + b4.z;
    y.w = d3 * rstd * g4.w + b4.w;
    *reinterpret_cast<float4*>(out + (size_t)row * DMODEL + tid * 4) = y;
    if (SPLIT) {
        size_t o0 = (size_t)row * DMODEL + tid * 4;
        uint32_t h0, l0, h1, l1;
        split2(y.x, y.y, h0, l0);
        split2(y.z, y.w, h1, l1);
        *reinterpret_cast<uint32_t*>(&outh[o0])     = h0;
        *reinterpret_cast<uint32_t*>(&outh[o0 + 2]) = h1;
        *reinterpret_cast<uint32_t*>(&outl[o0])     = l0;
        *reinterpret_cast<uint32_t*>(&outl[o0 + 2]) = l1;
    }
}

// ---------------- host-side orchestration ---------------------------------
extern "C" void kernel_launch(void* const* d_in, const int* in_sizes, int n_in,
                              void* d_out, int out_size) {
    const float* src = (const float*)d_in[0];
    const float* Wq = (const float*)d_in[1];
    const float* bq = (const float*)d_in[2];
    const float* Wk = (const float*)d_in[3];
    const float* bk = (const float*)d_in[4];
    const float* Wv = (const float*)d_in[5];
    const float* bv = (const float*)d_in[6];
    const float* Wo = (const float*)d_in[7];
    const float* bo = (const float*)d_in[8];
    const float* W1 = (const float*)d_in[9];
    const float* b1 = (const float*)d_in[10];
    const float* W2 = (const float*)d_in[11];
    const float* b2 = (const float*)d_in[12];
    const float* g1 = (const float*)d_in[13];
    const float* be1 = (const float*)d_in[14];
    const float* g2 = (const float*)d_in[15];
    const float* be2 = (const float*)d_in[16];
    float* outp = (float*)d_out;

    // resolve scratch symbols
    void* p;
#define SYM(name) cudaGetSymbolAddress(&p, name)
    __nv_bfloat16 *srch, *srcl, *qh, *ql, *kh, *kl, *vh, *vl;
    __nv_bfloat16 *ctxh, *ctxl, *x1h, *x1l, *hidh, *hidl, *wh, *wl;
    float *TMP, *X1;
    SYM(s_srch); srch = (__nv_bfloat16*)p;
    SYM(s_srcl); srcl = (__nv_bfloat16*)p;
    SYM(s_qh); qh = (__nv_bfloat16*)p;
    SYM(s_ql); ql = (__nv_bfloat16*)p;
    SYM(s_kh); kh = (__nv_bfloat16*)p;
    SYM(s_kl); kl = (__nv_bfloat16*)p;
    SYM(s_vh); vh = (__nv_bfloat16*)p;
    SYM(s_vl); vl = (__nv_bfloat16*)p;
    SYM(s_ctxh); ctxh = (__nv_bfloat16*)p;
    SYM(s_ctxl); ctxl = (__nv_bfloat16*)p;
    SYM(s_x1h); x1h = (__nv_bfloat16*)p;
    SYM(s_x1l); x1l = (__nv_bfloat16*)p;
    SYM(s_hidh); hidh = (__nv_bfloat16*)p;
    SYM(s_hidl); hidl = (__nv_bfloat16*)p;
    SYM(s_wh); wh = (__nv_bfloat16*)p;
    SYM(s_wl); wl = (__nv_bfloat16*)p;
    SYM(g_tmp); TMP = (float*)p;
    SYM(g_x1); X1 = (float*)p;
#undef SYM

    cudaFuncSetAttribute(attn_mma2, cudaFuncAttributeMaxDynamicSharedMemorySize,
                         ATTN_SMEM);
    cudaFuncSetAttribute(gemm_mma2<0>, cudaFuncAttributeMaxDynamicSharedMemorySize,
                         GEMM_SMEM);
    cudaFuncSetAttribute(gemm_mma2<1>, cudaFuncAttributeMaxDynamicSharedMemorySize,
                         GEMM_SMEM);
    cudaFuncSetAttribute(gemm_mma2<2>, cudaFuncAttributeMaxDynamicSharedMemorySize,
                         GEMM_SMEM);

    dim3 blk(256);
    dim3 grid_d(DMODEL / 128, MROWS / 128);   // (4, 64)
    dim3 grid_ff(DFF / 128, MROWS / 128);     // (16, 64)

    // ---- split src + weights ----
    split_kernel<<<ACT / 4 / 256, 256>>>(src, srch, srcl, ACT / 4);
    split_kernel<<<WSQ / 4 / 256, 256>>>(Wq, wh + OFF_WQ, wl + OFF_WQ, WSQ / 4);
    split_kernel<<<WSQ / 4 / 256, 256>>>(Wk, wh + OFF_WK, wl + OFF_WK, WSQ / 4);
    split_kernel<<<WSQ / 4 / 256, 256>>>(Wv, wh + OFF_WV, wl + OFF_WV, WSQ / 4);
    split_kernel<<<WSQ / 4 / 256, 256>>>(Wo, wh + OFF_WO, wl + OFF_WO, WSQ / 4);
    split_kernel<<<WFF / 4 / 256, 256>>>(W1, wh + OFF_W1, wl + OFF_W1, WFF / 4);
    split_kernel<<<WFF / 4 / 256, 256>>>(W2, wh + OFF_W2, wl + OFF_W2, WFF / 4);

    // ---- Q/K/V projections -> split [BH,T,64] ----
    gemm_mma2<0><<<grid_d, blk, GEMM_SMEM>>>(srch, srcl, wh + OFF_WQ, wl + OFF_WQ,
                                             bq, nullptr, nullptr, qh, ql,
                                             MROWS, DMODEL, DMODEL);
    gemm_mma2<0><<<grid_d, blk, GEMM_SMEM>>>(srch, srcl, wh + OFF_WK, wl + OFF_WK,
                                             bk, nullptr, nullptr, kh, kl,
                                             MROWS, DMODEL, DMODEL);
    gemm_mma2<0><<<grid_d, blk, GEMM_SMEM>>>(srch, srcl, wh + OFF_WV, wl + OFF_WV,
                                             bv, nullptr, nullptr, vh, vl,
                                             MROWS, DMODEL, DMODEL);

    // ---- attention -> split ctx [B,T,D] ----
    attn_mma2<<<dim3(SEQ / 128, BATCH * NHEAD), blk, ATTN_SMEM>>>(
        qh, ql, kh, kl, vh, vl, ctxh, ctxl);

    // ---- O-proj + bias + residual(src) -> TMP ; LN1 -> X1 fp32 + split ----
    gemm_mma2<1><<<grid_d, blk, GEMM_SMEM>>>(ctxh, ctxl, wh + OFF_WO, wl + OFF_WO,
                                             bo, src, TMP, nullptr, nullptr,
                                             MROWS, DMODEL, DMODEL);
    ln_kernel<1><<<MROWS, 128>>>(TMP, g1, be1, X1, x1h, x1l);

    // ---- FFN1 + GELU -> split HID ----
    gemm_mma2<2><<<grid_ff, blk, GEMM_SMEM>>>(x1h, x1l, wh + OFF_W1, wl + OFF_W1,
                                              b1, nullptr, nullptr, hidh, hidl,
                                              MROWS, DFF, DMODEL);

    // ---- FFN2 + bias + residual(X1) -> TMP ; LN2 -> out ----
    gemm_mma2<1><<<grid_d, blk, GEMM_SMEM>>>(hidh, hidl, wh + OFF_W2, wl + OFF_W2,
                                             b2, X1, TMP, nullptr, nullptr,
                                             MROWS, DMODEL, DFF);
    ln_kernel<0><<<MROWS, 128>>>(TMP, g2, be2, outp, nullptr, nullptr);
}

// round 16
// speedup vs baseline: 3.6935x; 1.0119x over previous
#include <cuda_runtime.h>
#include <cuda_bf16.h>
#include <math.h>
#include <stdint.h>

// Problem constants
#define BATCH 4
#define SEQ   2048
#define DMODEL 512
#define NHEAD 8
#define HDIM  64
#define DFF   2048
#define MROWS (BATCH * SEQ)   // 8192

#define ACT   (MROWS * DMODEL)        // 4,194,304
#define WSQ   (DMODEL * DMODEL)       // 262,144
#define WFF   (DFF * DMODEL)          // 1,048,576
#define WTOT  (4 * WSQ + 2 * WFF)     // 3,145,728

// weight offsets in combined split-weight buffers (WQ,WK,WV contiguous!)
#define OFF_WQ 0
#define OFF_WK (1 * WSQ)
#define OFF_WV (2 * WSQ)
#define OFF_WO (3 * WSQ)
#define OFF_W1 (4 * WSQ)
#define OFF_W2 (4 * WSQ + WFF)

// ---------------- scratch (static device arrays; no allocation allowed) ----
__device__ __nv_bfloat16 s_srch[ACT], s_srcl[ACT];
__device__ __nv_bfloat16 s_qh[ACT], s_ql[ACT];
__device__ __nv_bfloat16 s_kh[ACT], s_kl[ACT];
__device__ __nv_bfloat16 s_vh[ACT], s_vl[ACT];
__device__ __nv_bfloat16 s_ctxh[ACT], s_ctxl[ACT];
__device__ __nv_bfloat16 s_x1h[ACT], s_x1l[ACT];
__device__ __nv_bfloat16 s_hidh[MROWS * DFF], s_hidl[MROWS * DFF];
__device__ __nv_bfloat16 s_wh[WTOT], s_wl[WTOT];
__device__ float g_tmp[ACT];       // pre-LN fp32
__device__ float g_x1[ACT];        // post-LN1 fp32 (residual for FFN2)
__device__ float g_bias3[3 * DMODEL];  // concatenated bq|bk|bv

// ---------------- common helpers -------------------------------------------
__device__ __forceinline__ uint32_t smem_u32(const void* p) {
    return (uint32_t)__cvta_generic_to_shared(p);
}

__device__ __forceinline__ void ldmx4(uint32_t addr, uint32_t& r0, uint32_t& r1,
                                      uint32_t& r2, uint32_t& r3) {
    asm volatile("ldmatrix.sync.aligned.m8n8.x4.shared.b16 {%0,%1,%2,%3}, [%4];"
                 : "=r"(r0), "=r"(r1), "=r"(r2), "=r"(r3) : "r"(addr));
}

__device__ __forceinline__ void ldmx4t(uint32_t addr, uint32_t& r0, uint32_t& r1,
                                       uint32_t& r2, uint32_t& r3) {
    asm volatile("ldmatrix.sync.aligned.m8n8.x4.trans.shared.b16 {%0,%1,%2,%3}, [%4];"
                 : "=r"(r0), "=r"(r1), "=r"(r2), "=r"(r3) : "r"(addr));
}

__device__ __forceinline__ void mma_bf16(float* c, const uint32_t* a, const uint32_t* b) {
    asm volatile(
        "mma.sync.aligned.m16n8k16.row.col.f32.bf16.bf16.f32 "
        "{%0,%1,%2,%3}, {%4,%5,%6,%7}, {%8,%9}, {%0,%1,%2,%3};"
        : "+f"(c[0]), "+f"(c[1]), "+f"(c[2]), "+f"(c[3])
        : "r"(a[0]), "r"(a[1]), "r"(a[2]), "r"(a[3]), "r"(b[0]), "r"(b[1]));
}

__device__ __forceinline__ void split2(float x, float y, uint32_t& hi, uint32_t& lo) {
    __nv_bfloat16 xh = __float2bfloat16_rn(x);
    __nv_bfloat16 yh = __float2bfloat16_rn(y);
    __nv_bfloat16 xl = __float2bfloat16_rn(x - __bfloat162float(xh));
    __nv_bfloat16 yl = __float2bfloat16_rn(y - __bfloat162float(yh));
    __nv_bfloat162 h2(xh, yh), l2(xl, yl);
    hi = *reinterpret_cast<uint32_t*>(&h2);
    lo = *reinterpret_cast<uint32_t*>(&l2);
}

__device__ __forceinline__ float ex2(float x) {
    float y;
    asm("ex2.approx.f32 %0, %1;" : "=f"(y) : "f"(x));
    return y;
}

__device__ __forceinline__ void cpa16(uint32_t dst, const void* src) {
    asm volatile("cp.async.cg.shared.global [%0], [%1], 16;\n" ::"r"(dst), "l"(src));
}
__device__ __forceinline__ void cpa_commit() {
    asm volatile("cp.async.commit_group;\n" ::);
}
template <int N>
__device__ __forceinline__ void cpa_wait() {
    asm volatile("cp.async.wait_group %0;\n" ::"n"(N));
}

// ---------------- split pass: fp32 -> bf16 hi/lo ---------------------------
__global__ __launch_bounds__(256)
void split_kernel(const float* __restrict__ in, __nv_bfloat16* __restrict__ hi,
                  __nv_bfloat16* __restrict__ lo, int n4) {
    int i = blockIdx.x * blockDim.x + threadIdx.x;
    if (i < n4) {
        float4 v = reinterpret_cast<const float4*>(in)[i];
        uint32_t h0, l0, h1, l1;
        split2(v.x, v.y, h0, l0);
        split2(v.z, v.w, h1, l1);
        reinterpret_cast<uint32_t*>(hi)[i * 2]     = h0;
        reinterpret_cast<uint32_t*>(hi)[i * 2 + 1] = h1;
        reinterpret_cast<uint32_t*>(lo)[i * 2]     = l0;
        reinterpret_cast<uint32_t*>(lo)[i * 2 + 1] = l1;
    }
}

// ---------------- bias concat: bq|bk|bv -> g_bias3 -------------------------
__global__ __launch_bounds__(256)
void concat_bias(const float* __restrict__ a, const float* __restrict__ b,
                 const float* __restrict__ c, float* __restrict__ o) {
    int i = blockIdx.x * 256 + threadIdx.x;   // 0..1535
    float v = (i < 512) ? a[i] : (i < 1024) ? b[i - 512] : c[i - 1024];
    o[i] = v;
}

// ================= pre-split bf16 tensor-core GEMM =========================
// C = A (MxK) * B^T, A/B given as bf16 hi/lo arrays. 3 MMAs (hh+hl+lh).
// Block 128x128, BK=32, 256 threads (2m x 4n warps), cp.async double-buffered.
// __launch_bounds__(256,2): force <=128 regs so 2 CTAs/SM.
// EPI 0: fused QKV heads scatter + bias (out pair selected by n>>9)
// EPI 1: bias + residual -> fp32 out
// EPI 2: bias + GELU -> split bf16 out
#define LDK 40
#define GEMM_SZ (128 * LDK)                 // elements per smem array
#define GEMM_SMEM (2 * 4 * GEMM_SZ * 2)     // 81920 bytes

template <int EPI>
__global__ __launch_bounds__(256, 2)
void gemm_mma2(const __nv_bfloat16* __restrict__ Ah, const __nv_bfloat16* __restrict__ Al,
               const __nv_bfloat16* __restrict__ Bh, const __nv_bfloat16* __restrict__ Bl,
               const float* __restrict__ bias, const float* __restrict__ res,
               float* __restrict__ outf, __nv_bfloat16* __restrict__ outh,
               __nv_bfloat16* __restrict__ outl, __nv_bfloat16* __restrict__ outh2,
               __nv_bfloat16* __restrict__ outl2, __nv_bfloat16* __restrict__ outh3,
               __nv_bfloat16* __restrict__ outl3, int M, int N, int K) {
    extern __shared__ __nv_bfloat16 smg[];

    const int tid = threadIdx.x;
    const int warp = tid >> 5;
    const int lane = tid & 31;
    const int wm = (warp & 1) * 64;
    const int wn = (warp >> 1) * 32;
    const int bm = blockIdx.y * 128;
    const int bn = blockIdx.x * 128;
    const int mat = lane >> 3;
    const int mrw = lane & 7;

    float acc[4][4][4];
#pragma unroll
    for (int i = 0; i < 4; ++i)
#pragma unroll
        for (int j = 0; j < 4; ++j)
#pragma unroll
            for (int c = 0; c < 4; ++c) acc[i][j][c] = 0.0f;

    auto load_stage = [&](int k0, int st) {
        __nv_bfloat16* base = smg + st * 4 * GEMM_SZ;
#pragma unroll
        for (int it = 0; it < 2; ++it) {
            int idx = it * 256 + tid;           // 0..511
            int row = idx >> 2;
            int ch = (idx & 3) * 8;             // col (8 bf16 = 16B)
            int so = row * LDK + ch;
            size_t ga = (size_t)(bm + row) * K + k0 + ch;
            size_t gb = (size_t)(bn + row) * K + k0 + ch;
            cpa16(smem_u32(base + so), Ah + ga);
            cpa16(smem_u32(base + GEMM_SZ + so), Al + ga);
            cpa16(smem_u32(base + 2 * GEMM_SZ + so), Bh + gb);
            cpa16(smem_u32(base + 3 * GEMM_SZ + so), Bl + gb);
        }
    };

    const int nk = K / 32;
    load_stage(0, 0);
    cpa_commit();

    for (int i = 0; i < nk; ++i) {
        if (i + 1 < nk) {
            load_stage((i + 1) * 32, (i + 1) & 1);
            cpa_commit();
            cpa_wait<1>();
        } else {
            cpa_wait<0>();
        }
        __syncthreads();

        const __nv_bfloat16* base = smg + (i & 1) * 4 * GEMM_SZ;
        const __nv_bfloat16* sAh = base;
        const __nv_bfloat16* sAl = base + GEMM_SZ;
        const __nv_bfloat16* sBh = base + 2 * GEMM_SZ;
        const __nv_bfloat16* sBl = base + 3 * GEMM_SZ;

#pragma unroll
        for (int ks = 0; ks < 32; ks += 16) {
            uint32_t bhF[4][2], blF[4][2];
#pragma unroll
            for (int pair = 0; pair < 2; ++pair) {
                int atom = pair * 2 + (mat >> 1);
                int kc = ks + (mat & 1) * 8;
                int nrow = wn + atom * 8 + mrw;
                uint32_t r0, r1, r2, r3;
                ldmx4(smem_u32(&sBh[nrow * LDK + kc]), r0, r1, r2, r3);
                bhF[pair * 2][0] = r0; bhF[pair * 2][1] = r1;
                bhF[pair * 2 + 1][0] = r2; bhF[pair * 2 + 1][1] = r3;
                ldmx4(smem_u32(&sBl[nrow * LDK + kc]), r0, r1, r2, r3);
                blF[pair * 2][0] = r0; blF[pair * 2][1] = r1;
                blF[pair * 2 + 1][0] = r2; blF[pair * 2 + 1][1] = r3;
            }
#pragma unroll
            for (int am = 0; am < 4; ++am) {
                int arow = wm + am * 16 + (mat & 1) * 8 + mrw;
                int akc = ks + (mat >> 1) * 8;
                uint32_t ahF[4], alF[4];
                ldmx4(smem_u32(&sAh[arow * LDK + akc]), ahF[0], ahF[1], ahF[2], ahF[3]);
                ldmx4(smem_u32(&sAl[arow * LDK + akc]), alF[0], alF[1], alF[2], alF[3]);
#pragma unroll
                for (int an = 0; an < 4; ++an) {
                    mma_bf16(acc[am][an], ahF, bhF[an]);
                    mma_bf16(acc[am][an], ahF, blF[an]);
                    mma_bf16(acc[am][an], alF, bhF[an]);
                }
            }
        }
        __syncthreads();
    }

    // ---- epilogue ----
    const int gid = lane >> 2;
    const int tig = lane & 3;
#pragma unroll
    for (int am = 0; am < 4; ++am) {
#pragma unroll
        for (int an = 0; an < 4; ++an) {
            int m0 = bm + wm + am * 16 + gid;
            int m1 = m0 + 8;
            int n0 = bn + wn + an * 8 + tig * 2;
            float bs0 = bias[n0], bs1 = bias[n0 + 1];
            float v00 = acc[am][an][0] + bs0;
            float v01 = acc[am][an][1] + bs1;
            float v10 = acc[am][an][2] + bs0;
            float v11 = acc[am][an][3] + bs1;
            if (EPI == 0) {
                // fused QKV: proj = n0>>9 selects q/k/v; head within proj
                int proj = n0 >> 9;
                int hh = (n0 >> 6) & 7, dh = n0 & 63;
                __nv_bfloat16* OH = (proj == 0) ? outh : (proj == 1) ? outh2 : outh3;
                __nv_bfloat16* OL = (proj == 0) ? outl : (proj == 1) ? outl2 : outl3;
                size_t i0 = (((size_t)((m0 >> 11) * NHEAD + hh) * SEQ) + (m0 & 2047)) * HDIM + dh;
                size_t i1 = (((size_t)((m1 >> 11) * NHEAD + hh) * SEQ) + (m1 & 2047)) * HDIM + dh;
                uint32_t hw, lw;
                split2(v00, v01, hw, lw);
                *reinterpret_cast<uint32_t*>(&OH[i0]) = hw;
                *reinterpret_cast<uint32_t*>(&OL[i0]) = lw;
                split2(v10, v11, hw, lw);
                *reinterpret_cast<uint32_t*>(&OH[i1]) = hw;
                *reinterpret_cast<uint32_t*>(&OL[i1]) = lw;
            } else if (EPI == 1) {
                size_t o0 = (size_t)m0 * N + n0;
                size_t o1 = (size_t)m1 * N + n0;
                float2 r0 = *reinterpret_cast<const float2*>(&res[o0]);
                float2 r1 = *reinterpret_cast<const float2*>(&res[o1]);
                float2 w0 = {v00 + r0.x, v01 + r0.y};
                float2 w1 = {v10 + r1.x, v11 + r1.y};
                *reinterpret_cast<float2*>(&outf[o0]) = w0;
                *reinterpret_cast<float2*>(&outf[o1]) = w1;
            } else {
                size_t o0 = (size_t)m0 * N + n0;
                size_t o1 = (size_t)m1 * N + n0;
                float g00 = 0.5f * v00 * (1.0f + erff(v00 * 0.70710678118654752f));
                float g01 = 0.5f * v01 * (1.0f + erff(v01 * 0.70710678118654752f));
                float g10 = 0.5f * v10 * (1.0f + erff(v10 * 0.70710678118654752f));
                float g11 = 0.5f * v11 * (1.0f + erff(v11 * 0.70710678118654752f));
                uint32_t hw, lw;
                split2(g00, g01, hw, lw);
                *reinterpret_cast<uint32_t*>(&outh[o0]) = hw;
                *reinterpret_cast<uint32_t*>(&outl[o0]) = lw;
                split2(g10, g11, hw, lw);
                *reinterpret_cast<uint32_t*>(&outh[o1]) = hw;
                *reinterpret_cast<uint32_t*>(&outl[o1]) = lw;
            }
        }
    }
}

// ================= tensor-core flash attention (pre-split bf16) ============
// grid (SEQ/128=16, BH=32). 256 threads (8 warps), 16 q rows/warp, 64-key tiles.
// V k-major; PV B-fragments via ldmatrix.trans. K/V double-buffered cp.async.
// Softmax in base-2: scale folds 1/8 * log2(e); all exp via raw ex2.
#define ALD 72
#define KVSZ (64 * ALD)                                  // elements per K/V array
#define ATTN_SMEM ((2 * 128 * ALD + 2 * 4 * KVSZ) * 2)   // 110592 bytes
#define S2SCALE 0.18033688011112042f                      // 0.125 * log2(e)

__global__ __launch_bounds__(256, 2)
void attn_mma2(const __nv_bfloat16* __restrict__ qh, const __nv_bfloat16* __restrict__ ql,
               const __nv_bfloat16* __restrict__ kh, const __nv_bfloat16* __restrict__ kl,
               const __nv_bfloat16* __restrict__ vh, const __nv_bfloat16* __restrict__ vl,
               __nv_bfloat16* __restrict__ ctxh, __nv_bfloat16* __restrict__ ctxl) {
    extern __shared__ __nv_bfloat16 sm[];
    __nv_bfloat16* sQh = sm;                     // [128][ALD]
    __nv_bfloat16* sQl = sQh + 128 * ALD;
    __nv_bfloat16* stage = sQl + 128 * ALD;      // 2 x {Kh,Kl,Vh,Vl} [64][ALD]

    const int qt = blockIdx.x;
    const int bh = blockIdx.y;
    const int b = bh >> 3;
    const int h = bh & 7;
    const int tid = threadIdx.x;
    const int warp = tid >> 5;
    const int lane = tid & 31;
    const int mat = lane >> 3;
    const int mrw = lane & 7;
    const int gid = lane >> 2;
    const int tig = lane & 3;

    const size_t qoff = ((size_t)bh * SEQ + qt * 128) * HDIM;
    const size_t koff = (size_t)bh * SEQ * HDIM;

    auto load_kv = [&](int kt, int st) {
        const size_t toff = koff + (size_t)kt * 64 * HDIM;
        __nv_bfloat16* bs = stage + st * 4 * KVSZ;
#pragma unroll
        for (int it = 0; it < 2; ++it) {
            int idx = it * 256 + tid;
            int row = idx >> 3;
            int ch = (idx & 7) * 8;
            int so = row * ALD + ch;
            size_t g = toff + row * HDIM + ch;
            cpa16(smem_u32(bs + so), kh + g);
            cpa16(smem_u32(bs + KVSZ + so), kl + g);
            cpa16(smem_u32(bs + 2 * KVSZ + so), vh + g);
            cpa16(smem_u32(bs + 3 * KVSZ + so), vl + g);
        }
    };

    load_kv(0, 0);
    cpa_commit();

#pragma unroll
    for (int it = 0; it < 4; ++it) {
        int idx = it * 256 + tid;
        int row = idx >> 3;
        int ch = (idx & 7) * 8;
        int so = row * ALD + ch;
        *reinterpret_cast<uint4*>(&sQh[so]) =
            *reinterpret_cast<const uint4*>(&qh[qoff + row * HDIM + ch]);
        *reinterpret_cast<uint4*>(&sQl[so]) =
            *reinterpret_cast<const uint4*>(&ql[qoff + row * HDIM + ch]);
    }

    float o[8][4];
#pragma unroll
    for (int j = 0; j < 8; ++j)
#pragma unroll
        for (int c = 0; c < 4; ++c) o[j][c] = 0.0f;
    float m0 = -1e30f, m1 = -1e30f, l0r = 0.0f, l1r = 0.0f;

    const int NT = SEQ / 64;
    for (int kt = 0; kt < NT; ++kt) {
        if (kt + 1 < NT) {
            load_kv(kt + 1, (kt + 1) & 1);
            cpa_commit();
            cpa_wait<1>();
        } else {
            cpa_wait<0>();
        }
        __syncthreads();

        const __nv_bfloat16* bs = stage + (kt & 1) * 4 * KVSZ;
        const __nv_bfloat16* sKh = bs;
        const __nv_bfloat16* sKl = bs + KVSZ;
        const __nv_bfloat16* sVh = bs + 2 * KVSZ;
        const __nv_bfloat16* sVl = bs + 3 * KVSZ;

        float sa[8][4];
#pragma unroll
        for (int j = 0; j < 8; ++j)
#pragma unroll
            for (int c = 0; c < 4; ++c) sa[j][c] = 0.0f;

#pragma unroll
        for (int s = 0; s < 4; ++s) {
            int akc = 16 * s + (mat >> 1) * 8;
            int arow = 16 * warp + (mat & 1) * 8 + mrw;
            uint32_t qhF[4], qlF[4];
            ldmx4(smem_u32(&sQh[arow * ALD + akc]), qhF[0], qhF[1], qhF[2], qhF[3]);
            ldmx4(smem_u32(&sQl[arow * ALD + akc]), qlF[0], qlF[1], qlF[2], qlF[3]);
            uint32_t khF[8][2], klF[8][2];
#pragma unroll
            for (int pair = 0; pair < 4; ++pair) {
                int atom = pair * 2 + (mat >> 1);
                int kc = 16 * s + (mat & 1) * 8;
                int nrow = atom * 8 + mrw;
                uint32_t r0, r1, r2, r3;
                ldmx4(smem_u32(&sKh[nrow * ALD + kc]), r0, r1, r2, r3);
                khF[pair * 2][0] = r0; khF[pair * 2][1] = r1;
                khF[pair * 2 + 1][0] = r2; khF[pair * 2 + 1][1] = r3;
                ldmx4(smem_u32(&sKl[nrow * ALD + kc]), r0, r1, r2, r3);
                klF[pair * 2][0] = r0; klF[pair * 2][1] = r1;
                klF[pair * 2 + 1][0] = r2; klF[pair * 2 + 1][1] = r3;
            }
#pragma unroll
            for (int j = 0; j < 8; ++j) {
                mma_bf16(sa[j], qhF, khF[j]);
                mma_bf16(sa[j], qhF, klF[j]);
                mma_bf16(sa[j], qlF, khF[j]);
            }
        }

        // ---- online softmax (base-2 domain) ----
        float mx0 = -1e30f, mx1 = -1e30f;
#pragma unroll
        for (int j = 0; j < 8; ++j) {
            sa[j][0] *= S2SCALE; sa[j][1] *= S2SCALE;
            sa[j][2] *= S2SCALE; sa[j][3] *= S2SCALE;
            mx0 = fmaxf(mx0, fmaxf(sa[j][0], sa[j][1]));
            mx1 = fmaxf(mx1, fmaxf(sa[j][2], sa[j][3]));
        }
        mx0 = fmaxf(mx0, __shfl_xor_sync(0xffffffffu, mx0, 1));
        mx0 = fmaxf(mx0, __shfl_xor_sync(0xffffffffu, mx0, 2));
        mx1 = fmaxf(mx1, __shfl_xor_sync(0xffffffffu, mx1, 1));
        mx1 = fmaxf(mx1, __shfl_xor_sync(0xffffffffu, mx1, 2));
        float mn0 = fmaxf(m0, mx0), mn1 = fmaxf(m1, mx1);
        float f0 = ex2(m0 - mn0), f1 = ex2(m1 - mn1);

        float rs0 = 0.0f, rs1 = 0.0f;
        uint32_t ph2[8][2], pl2[8][2];
#pragma unroll
        for (int j = 0; j < 8; ++j) {
            float p0 = ex2(sa[j][0] - mn0);
            float p1 = ex2(sa[j][1] - mn0);
            float p2 = ex2(sa[j][2] - mn1);
            float p3 = ex2(sa[j][3] - mn1);
            rs0 += p0 + p1;
            rs1 += p2 + p3;
            split2(p0, p1, ph2[j][0], pl2[j][0]);
            split2(p2, p3, ph2[j][1], pl2[j][1]);
            o[j][0] *= f0; o[j][1] *= f0;
            o[j][2] *= f1; o[j][3] *= f1;
        }
        rs0 += __shfl_xor_sync(0xffffffffu, rs0, 1);
        rs0 += __shfl_xor_sync(0xffffffffu, rs0, 2);
        rs1 += __shfl_xor_sync(0xffffffffu, rs1, 1);
        rs1 += __shfl_xor_sync(0xffffffffu, rs1, 2);
        l0r = l0r * f0 + rs0;
        l1r = l1r * f1 + rs1;
        m0 = mn0; m1 = mn1;

        // ---- O += P V : B-fragments via ldmatrix.trans on k-major V ----
#pragma unroll
        for (int s = 0; s < 4; ++s) {
            uint32_t pah[4] = {ph2[2 * s][0], ph2[2 * s][1],
                               ph2[2 * s + 1][0], ph2[2 * s + 1][1]};
            uint32_t pal[4] = {pl2[2 * s][0], pl2[2 * s][1],
                               pl2[2 * s + 1][0], pl2[2 * s + 1][1]};
            uint32_t vhF[8][2], vlF[8][2];
#pragma unroll
            for (int pair = 0; pair < 4; ++pair) {
                int krow = 16 * s + (mat & 1) * 8 + mrw;
                int dcol = (pair * 2 + (mat >> 1)) * 8;
                uint32_t r0, r1, r2, r3;
                ldmx4t(smem_u32(&sVh[krow * ALD + dcol]), r0, r1, r2, r3);
                vhF[pair * 2][0] = r0; vhF[pair * 2][1] = r1;
                vhF[pair * 2 + 1][0] = r2; vhF[pair * 2 + 1][1] = r3;
                ldmx4t(smem_u32(&sVl[krow * ALD + dcol]), r0, r1, r2, r3);
                vlF[pair * 2][0] = r0; vlF[pair * 2][1] = r1;
                vlF[pair * 2 + 1][0] = r2; vlF[pair * 2 + 1][1] = r3;
            }
#pragma unroll
            for (int j = 0; j < 8; ++j) {
                mma_bf16(o[j], pah, vhF[j]);
                mma_bf16(o[j], pah, vlF[j]);
                mma_bf16(o[j], pal, vhF[j]);
            }
        }
        __syncthreads();
    }

    float inv0 = 1.0f / l0r;
    float inv1 = 1.0f / l1r;
    int t0 = qt * 128 + warp * 16 + gid;
    int t1 = t0 + 8;
#pragma unroll
    for (int j = 0; j < 8; ++j) {
        int col = h * HDIM + j * 8 + tig * 2;
        size_t i0 = ((size_t)(b * SEQ + t0)) * DMODEL + col;
        size_t i1 = ((size_t)(b * SEQ + t1)) * DMODEL + col;
        uint32_t hw, lw;
        split2(o[j][0] * inv0, o[j][1] * inv0, hw, lw);
        *reinterpret_cast<uint32_t*>(&ctxh[i0]) = hw;
        *reinterpret_cast<uint32_t*>(&ctxl[i0]) = lw;
        split2(o[j][2] * inv1, o[j][3] * inv1, hw, lw);
        *reinterpret_cast<uint32_t*>(&ctxh[i1]) = hw;
        *reinterpret_cast<uint32_t*>(&ctxl[i1]) = lw;
    }
}

// ---------------- LayerNorm (optionally emits split bf16 too) --------------
template <int SPLIT>
__global__ __launch_bounds__(128)
void ln_kernel(const float* __restrict__ in, const float* __restrict__ g,
               const float* __restrict__ beta, float* __restrict__ out,
               __nv_bfloat16* __restrict__ outh, __nv_bfloat16* __restrict__ outl) {
    __shared__ float red[8];
    const int row = blockIdx.x;
    const int tid = threadIdx.x;
    const int lane = tid & 31;
    const int wid = tid >> 5;

    float4 x4 = *reinterpret_cast<const float4*>(in + (size_t)row * DMODEL + tid * 4);
    float s = x4.x + x4.y + x4.z + x4.w;
#pragma unroll
    for (int off = 16; off; off >>= 1) s += __shfl_xor_sync(0xffffffffu, s, off);
    if (lane == 0) red[wid] = s;
    __syncthreads();
    float mean = (red[0] + red[1] + red[2] + red[3]) * (1.0f / DMODEL);

    float d0 = x4.x - mean, d1 = x4.y - mean, d2 = x4.z - mean, d3 = x4.w - mean;
    float sq = d0 * d0 + d1 * d1 + d2 * d2 + d3 * d3;
#pragma unroll
    for (int off = 16; off; off >>= 1) sq += __shfl_xor_sync(0xffffffffu, sq, off);
    if (lane == 0) red[4 + wid] = sq;
    __syncthreads();
    float var = (red[4] + red[5] + red[6] + red[7]) * (1.0f / DMODEL);
    float rstd = rsqrtf(var + 1e-5f);

    float4 g4 = *reinterpret_cast<const float4*>(g + tid * 4);
    float4 b4 = *reinterpret_cast<const float4*>(beta + tid * 4);
    float4 y;
    y.x = d0 * rstd * g4.x + b4.x;
    y.y = d1 * rstd * g4.y + b4.y;
    y.z = d2 * rstd * g4.z + b4.z;
    y.w = d3 * rstd * g4.w + b4.w;
    *reinterpret_cast<float4*>(out + (size_t)row * DMODEL + tid * 4) = y;
    if (SPLIT) {
        size_t o0 = (size_t)row * DMODEL + tid * 4;
        uint32_t h0, l0, h1, l1;
        split2(y.x, y.y, h0, l0);
        split2(y.z, y.w, h1, l1);
        *reinterpret_cast<uint32_t*>(&outh[o0])     = h0;
        *reinterpret_cast<uint32_t*>(&outh[o0 + 2]) = h1;
        *reinterpret_cast<uint32_t*>(&outl[o0])     = l0;
        *reinterpret_cast<uint32_t*>(&outl[o0 + 2]) = l1;
    }
}

// ---------------- host-side orchestration ---------------------------------
extern "C" void kernel_launch(void* const* d_in, const int* in_sizes, int n_in,
                              void* d_out, int out_size) {
    const float* src = (const float*)d_in[0];
    const float* Wq = (const float*)d_in[1];
    const float* bq = (const float*)d_in[2];
    const float* Wk = (const float*)d_in[3];
    const float* bk = (const float*)d_in[4];
    const float* Wv = (const float*)d_in[5];
    const float* bv = (const float*)d_in[6];
    const float* Wo = (const float*)d_in[7];
    const float* bo = (const float*)d_in[8];
    const float* W1 = (const float*)d_in[9];
    const float* b1 = (const float*)d_in[10];
    const float* W2 = (const float*)d_in[11];
    const float* b2 = (const float*)d_in[12];
    const float* g1 = (const float*)d_in[13];
    const float* be1 = (const float*)d_in[14];
    const float* g2 = (const float*)d_in[15];
    const float* be2 = (const float*)d_in[16];
    float* outp = (float*)d_out;

    void* p;
#define SYM(name) cudaGetSymbolAddress(&p, name)
    __nv_bfloat16 *srch, *srcl, *qh, *ql, *kh, *kl, *vh, *vl;
    __nv_bfloat16 *ctxh, *ctxl, *x1h, *x1l, *hidh, *hidl, *wh, *wl;
    float *TMP, *X1, *BIAS3;
    SYM(s_srch); srch = (__nv_bfloat16*)p;
    SYM(s_srcl); srcl = (__nv_bfloat16*)p;
    SYM(s_qh); qh = (__nv_bfloat16*)p;
    SYM(s_ql); ql = (__nv_bfloat16*)p;
    SYM(s_kh); kh = (__nv_bfloat16*)p;
    SYM(s_kl); kl = (__nv_bfloat16*)p;
    SYM(s_vh); vh = (__nv_bfloat16*)p;
    SYM(s_vl); vl = (__nv_bfloat16*)p;
    SYM(s_ctxh); ctxh = (__nv_bfloat16*)p;
    SYM(s_ctxl); ctxl = (__nv_bfloat16*)p;
    SYM(s_x1h); x1h = (__nv_bfloat16*)p;
    SYM(s_x1l); x1l = (__nv_bfloat16*)p;
    SYM(s_hidh); hidh = (__nv_bfloat16*)p;
    SYM(s_hidl); hidl = (__nv_bfloat16*)p;
    SYM(s_wh); wh = (__nv_bfloat16*)p;
    SYM(s_wl); wl = (__nv_bfloat16*)p;
    SYM(g_tmp); TMP = (float*)p;
    SYM(g_x1); X1 = (float*)p;
    SYM(g_bias3); BIAS3 = (float*)p;
#undef SYM

    cudaFuncSetAttribute(attn_mma2, cudaFuncAttributeMaxDynamicSharedMemorySize,
                         ATTN_SMEM);
    cudaFuncSetAttribute(gemm_mma2<0>, cudaFuncAttributeMaxDynamicSharedMemorySize,
                         GEMM_SMEM);
    cudaFuncSetAttribute(gemm_mma2<1>, cudaFuncAttributeMaxDynamicSharedMemorySize,
                         GEMM_SMEM);
    cudaFuncSetAttribute(gemm_mma2<2>, cudaFuncAttributeMaxDynamicSharedMemorySize,
                         GEMM_SMEM);

    dim3 blk(256);
    dim3 grid_d(DMODEL / 128, MROWS / 128);     // (4, 64)
    dim3 grid_qkv(3 * DMODEL / 128, MROWS / 128);  // (12, 64) fused QKV
    dim3 grid_ff(DFF / 128, MROWS / 128);       // (16, 64)

    // ---- split src + weights, concat QKV bias ----
    split_kernel<<<ACT / 4 / 256, 256>>>(src, srch, srcl, ACT / 4);
    split_kernel<<<WSQ / 4 / 256, 256>>>(Wq, wh + OFF_WQ, wl + OFF_WQ, WSQ / 4);
    split_kernel<<<WSQ / 4 / 256, 256>>>(Wk, wh + OFF_WK, wl + OFF_WK, WSQ / 4);
    split_kernel<<<WSQ / 4 / 256, 256>>>(Wv, wh + OFF_WV, wl + OFF_WV, WSQ / 4);
    split_kernel<<<WSQ / 4 / 256, 256>>>(Wo, wh + OFF_WO, wl + OFF_WO, WSQ / 4);
    split_kernel<<<WFF / 4 / 256, 256>>>(W1, wh + OFF_W1, wl + OFF_W1, WFF / 4);
    split_kernel<<<WFF / 4 / 256, 256>>>(W2, wh + OFF_W2, wl + OFF_W2, WFF / 4);
    concat_bias<<<6, 256>>>(bq, bk, bv, BIAS3);

    // ---- fused Q/K/V projection -> split [BH,T,64] x3 ----
    gemm_mma2<0><<<grid_qkv, blk, GEMM_SMEM>>>(srch, srcl, wh + OFF_WQ, wl + OFF_WQ,
                                               BIAS3, nullptr, nullptr,
                                               qh, ql, kh, kl, vh, vl,
                                               MROWS, 3 * DMODEL, DMODEL);

    // ---- attention -> split ctx [B,T,D] ----
    attn_mma2<<<dim3(SEQ / 128, BATCH * NHEAD), blk, ATTN_SMEM>>>(
        qh, ql, kh, kl, vh, vl, ctxh, ctxl);

    // ---- O-proj + bias + residual(src) -> TMP ; LN1 -> X1 fp32 + split ----
    gemm_mma2<1><<<grid_d, blk, GEMM_SMEM>>>(ctxh, ctxl, wh + OFF_WO, wl + OFF_WO,
                                             bo, src, TMP, nullptr, nullptr,
                                             nullptr, nullptr, nullptr, nullptr,
                                             MROWS, DMODEL, DMODEL);
    ln_kernel<1><<<MROWS, 128>>>(TMP, g1, be1, X1, x1h, x1l);

    // ---- FFN1 + GELU -> split HID ----
    gemm_mma2<2><<<grid_ff, blk, GEMM_SMEM>>>(x1h, x1l, wh + OFF_W1, wl + OFF_W1,
                                              b1, nullptr, nullptr, hidh, hidl,
                                              nullptr, nullptr, nullptr, nullptr,
                                              MROWS, DFF, DMODEL);

    // ---- FFN2 + bias + residual(X1) -> TMP ; LN2 -> out ----
    gemm_mma2<1><<<grid_d, blk, GEMM_SMEM>>>(hidh, hidl, wh + OFF_W2, wl + OFF_W2,
                                             b2, X1, TMP, nullptr, nullptr,
                                             nullptr, nullptr, nullptr, nullptr,
                                             MROWS, DMODEL, DFF);
    ln_kernel<0><<<MROWS, 128>>>(TMP, g2, be2, outp, nullptr, nullptr);
}